// round 8
// baseline (speedup 1.0000x reference)
#include <cuda_runtime.h>
#include <cuda_bf16.h>
#include <cstdint>

// Problem constants
#define NN 50000
#define NE 150000
#define DF 512
#define NH 512
#define NC 47
#define NADJ (NE + NN)

// ---------------- scratch (static __device__ — no allocation) ----------------
__device__ int   g_deg[NN];
__device__ __align__(16) float g_dinv[NN];
__device__ int   g_incl[NN];
__device__ int   g_bsum[128];
__device__ int   g_offs[NN + 1];
__device__ int   g_cursor[NN];
__device__ int   g_adj[NADJ];
__device__ __align__(16) float g_h1[(size_t)NN * NH];   // dinv-scaled x@W1
__device__ __align__(16) float g_a1[(size_t)NN * NH];   // relu(agg1 + b1)
__device__ __align__(16) float g_h2[(size_t)NN * NC];   // dinv-scaled layer2 pre-agg

// ---------------- graph prep ----------------
__global__ void k_init_deg() {
    int i = blockIdx.x * blockDim.x + threadIdx.x;
    if (i < NN) g_deg[i] = 1;  // self loop
}

__global__ void k_count_deg(const int* __restrict__ ecol) {
    int e = blockIdx.x * blockDim.x + threadIdx.x;
    if (e < NE) atomicAdd(&g_deg[ecol[e]], 1);
}

__global__ void k_scan_block() {
    __shared__ int s[512];
    int i = blockIdx.x * 512 + threadIdx.x;
    int v = (i < NN) ? g_deg[i] : 0;
    s[threadIdx.x] = v;
    __syncthreads();
    for (int off = 1; off < 512; off <<= 1) {
        int t = (threadIdx.x >= off) ? s[threadIdx.x - off] : 0;
        __syncthreads();
        s[threadIdx.x] += t;
        __syncthreads();
    }
    if (i < NN) g_incl[i] = s[threadIdx.x];
    if (threadIdx.x == 511) g_bsum[blockIdx.x] = s[511];
}

// parallel exclusive scan of the 98 block sums (one 128-thread block)
__global__ void k_scan_bsum(int nblocks) {
    __shared__ int s[128];
    int t = threadIdx.x;
    int v = (t < nblocks) ? g_bsum[t] : 0;
    s[t] = v;
    __syncthreads();
    for (int off = 1; off < 128; off <<= 1) {
        int u = (t >= off) ? s[t - off] : 0;
        __syncthreads();
        s[t] += u;
        __syncthreads();
    }
    if (t < nblocks) g_bsum[t] = s[t] - v;  // exclusive
}

__global__ void k_scan_finish() {
    int i = blockIdx.x * blockDim.x + threadIdx.x;
    if (i < NN) {
        int e = g_incl[i] - g_deg[i] + g_bsum[i / 512];
        g_offs[i] = e;
        g_cursor[i] = e;
        g_dinv[i] = rsqrtf((float)g_deg[i]);
    }
    if (i == 0) g_offs[NN] = NADJ;
}

__global__ void k_scatter(const int* __restrict__ erow,
                          const int* __restrict__ ecol) {
    int t = blockIdx.x * blockDim.x + threadIdx.x;
    if (t < NE) {
        int c = ecol[t];
        int p = atomicAdd(&g_cursor[c], 1);
        g_adj[p] = erow[t];
    } else if (t < NADJ) {
        int i = t - NE;
        int p = atomicAdd(&g_cursor[i], 1);
        g_adj[p] = i;
    }
}

// ---------------- helpers ----------------
__device__ __forceinline__ uint32_t f2tf32(float f) {
    uint32_t u;
    asm("cvt.rna.tf32.f32 %0, %1;" : "=r"(u) : "f"(f));
    return u;
}

__device__ __forceinline__ void mma_tf32(float& c0, float& c1, float& c2, float& c3,
                                         uint32_t a0, uint32_t a1, uint32_t a2, uint32_t a3,
                                         uint32_t b0, uint32_t b1) {
    asm volatile(
        "mma.sync.aligned.m16n8k8.row.col.f32.tf32.tf32.f32 "
        "{%0,%1,%2,%3},{%4,%5,%6,%7},{%8,%9},{%0,%1,%2,%3};"
        : "+f"(c0), "+f"(c1), "+f"(c2), "+f"(c3)
        : "r"(a0), "r"(a1), "r"(a2), "r"(a3), "r"(b0), "r"(b1));
}

__device__ __forceinline__ void cp16(uint32_t dst_smem, const void* src, bool pred) {
    int sz = pred ? 16 : 0;
    asm volatile("cp.async.cg.shared.global [%0], [%1], 16, %2;\n"
                 :: "r"(dst_smem), "l"(src), "r"(sz));
}

// ---------------- GEMM1 (TF32, 2-stage cp.async pipeline) ----------------
// g_h1[m,f] = dinv[m] * sum_k x[m,k] * W1[k,f]
// BM=128, BN=128, BK=32; 128 threads = 4 warps (2M x 2N); warp tile 64x64.
#define G1_ASTRIDE 36
#define G1_BSTRIDE 136
#define G1_AELEMS (128 * G1_ASTRIDE)
#define G1_STAGE  (G1_AELEMS + 32 * G1_BSTRIDE)
#define G1_SMEM_BYTES (2 * G1_STAGE * 4)

__global__ __launch_bounds__(128) void k_gemm1_tf32(const float* __restrict__ A,
                                                    const float* __restrict__ B) {
    extern __shared__ __align__(16) uint32_t dynsm[];

    const int tid = threadIdx.x;
    const int lane = tid & 31;
    const int warp = tid >> 5;
    const int wm = warp & 1;
    const int wn = warp >> 1;
    const int gp = lane >> 2;
    const int tq = lane & 3;

    const int rowBase = blockIdx.y * 128;
    const int colBase = blockIdx.x * 128;
    const int warpRow = wm * 64;
    const int warpCol = wn * 64;

    uint32_t smem_u32 = (uint32_t)__cvta_generic_to_shared((void*)dynsm);

    float acc[4][8][4];
#pragma unroll
    for (int mi = 0; mi < 4; mi++)
#pragma unroll
        for (int ni = 0; ni < 8; ni++)
#pragma unroll
            for (int j = 0; j < 4; j++) acc[mi][ni][j] = 0.f;

    const int NT = DF / 32;

    auto load_stage = [&](int st, int k0) {
        uint32_t aBase = smem_u32 + (uint32_t)(st * G1_STAGE) * 4u;
        uint32_t bBase = aBase + (uint32_t)G1_AELEMS * 4u;
#pragma unroll
        for (int i = 0; i < 8; i++) {
            int fid = tid + i * 128;
            int r = fid >> 3, q = fid & 7;
            int gr = rowBase + r;
            bool ok = gr < NN;
            const float* src = A + (size_t)(ok ? gr : 0) * DF + k0 + q * 4;
            cp16(aBase + (uint32_t)(r * G1_ASTRIDE + q * 4) * 4u, src, ok);
        }
#pragma unroll
        for (int i = 0; i < 8; i++) {
            int fid = tid + i * 128;
            int r = fid >> 5, q = fid & 31;
            const float* src = B + (size_t)(k0 + r) * NH + colBase + q * 4;
            cp16(bBase + (uint32_t)(r * G1_BSTRIDE + q * 4) * 4u, src, true);
        }
    };

    load_stage(0, 0);
    asm volatile("cp.async.commit_group;\n");

    for (int t = 0; t < NT; t++) {
        if (t + 1 < NT) load_stage((t + 1) & 1, (t + 1) * 32);
        asm volatile("cp.async.commit_group;\n");
        if (t + 1 < NT) asm volatile("cp.async.wait_group 1;\n");
        else            asm volatile("cp.async.wait_group 0;\n");
        __syncthreads();

        const uint32_t* AsS = dynsm + (t & 1) * G1_STAGE;
        const uint32_t* BsS = AsS + G1_AELEMS;

#pragma unroll
        for (int kk = 0; kk < 32; kk += 8) {
            uint32_t a[4][4];
#pragma unroll
            for (int mi = 0; mi < 4; mi++) {
                int r0 = warpRow + mi * 16 + gp;
                a[mi][0] = f2tf32(__uint_as_float(AsS[r0 * G1_ASTRIDE + kk + tq]));
                a[mi][1] = f2tf32(__uint_as_float(AsS[(r0 + 8) * G1_ASTRIDE + kk + tq]));
                a[mi][2] = f2tf32(__uint_as_float(AsS[r0 * G1_ASTRIDE + kk + tq + 4]));
                a[mi][3] = f2tf32(__uint_as_float(AsS[(r0 + 8) * G1_ASTRIDE + kk + tq + 4]));
            }
            uint32_t b[8][2];
#pragma unroll
            for (int ni = 0; ni < 8; ni++) {
                int c = warpCol + ni * 8 + gp;
                b[ni][0] = f2tf32(__uint_as_float(BsS[(kk + tq) * G1_BSTRIDE + c]));
                b[ni][1] = f2tf32(__uint_as_float(BsS[(kk + tq + 4) * G1_BSTRIDE + c]));
            }
#pragma unroll
            for (int mi = 0; mi < 4; mi++)
#pragma unroll
                for (int ni = 0; ni < 8; ni++)
                    mma_tf32(acc[mi][ni][0], acc[mi][ni][1],
                             acc[mi][ni][2], acc[mi][ni][3],
                             a[mi][0], a[mi][1], a[mi][2], a[mi][3],
                             b[ni][0], b[ni][1]);
        }
        __syncthreads();
    }

#pragma unroll
    for (int mi = 0; mi < 4; mi++) {
        int r0 = rowBase + warpRow + mi * 16 + gp;
        int r1 = r0 + 8;
        float d0 = (r0 < NN) ? g_dinv[r0] : 0.f;
        float d1 = (r1 < NN) ? g_dinv[r1] : 0.f;
#pragma unroll
        for (int ni = 0; ni < 8; ni++) {
            int c = colBase + warpCol + ni * 8 + tq * 2;
            if (r0 < NN) {
                float2 o = make_float2(d0 * acc[mi][ni][0], d0 * acc[mi][ni][1]);
                *(float2*)(g_h1 + (size_t)r0 * NH + c) = o;
            }
            if (r1 < NN) {
                float2 o = make_float2(d1 * acc[mi][ni][2], d1 * acc[mi][ni][3]);
                *(float2*)(g_h1 + (size_t)r1 * NH + c) = o;
            }
        }
    }
}

// ---------------- agg1: a1[i,f] = relu(dinv[i]*sum_{adj} h1[row,f] + b1[f]) ----------------
__global__ __launch_bounds__(128) void k_agg1(const float* __restrict__ b1) {
    const int node = blockIdx.x;
    const int f = threadIdx.x * 4;
    const int s = g_offs[node], e = g_offs[node + 1];
    float4 acc = make_float4(0.f, 0.f, 0.f, 0.f);
    for (int p = s; p < e; p++) {
        int r = g_adj[p];
        float4 v = *(const float4*)(g_h1 + (size_t)r * NH + f);
        acc.x += v.x; acc.y += v.y; acc.z += v.z; acc.w += v.w;
    }
    float d = g_dinv[node];
    float4 bb = *(const float4*)(b1 + f);
    float4 o;
    o.x = fmaxf(d * acc.x + bb.x, 0.f);
    o.y = fmaxf(d * acc.y + bb.y, 0.f);
    o.z = fmaxf(d * acc.z + bb.z, 0.f);
    o.w = fmaxf(d * acc.w + bb.w, 0.f);
    *(float4*)(g_a1 + (size_t)node * NH + f) = o;
}

// ---------------- GEMM2 (TF32, W2 resident in SMEM + 2-stage cp.async A pipeline) ----
// g_h2[m,c] = dinv[m] * sum_k a1[m,k] * W2[k,c]
// BM=128, BN=48 (covers NC=47); 256 threads = 8 warps, ALL on M (warp tile 16x48).
#define G2_ASTRIDE 36
#define G2_AELEMS (128 * G2_ASTRIDE)        // per stage (words)
#define G2_BSTRIDE 56                       // >=48; banks (56*tq+gp)%32 = {gp,8+gp,16+gp,24+gp} distinct
#define G2_BELEMS (NH * G2_BSTRIDE)         // 512*56 = 28672 words
#define G2_SMEM_BYTES ((2 * G2_AELEMS + G2_BELEMS) * 4)   // 36864+114688 = 151552 B

__global__ __launch_bounds__(256) void k_gemm2_tf32(const float* __restrict__ B) {
    extern __shared__ __align__(16) uint32_t dynsm[];
    uint32_t* Bw = dynsm + 2 * G2_AELEMS;   // [NH][G2_BSTRIDE] tf32 weights

    const int tid = threadIdx.x;
    const int lane = tid & 31;
    const int warp = tid >> 5;        // 0..7, all-M
    const int gp = lane >> 2;
    const int tq = lane & 3;

    const int rowBase = blockIdx.x * 128;
    const int warpRow = warp * 16;

    uint32_t smem_u32 = (uint32_t)__cvta_generic_to_shared((void*)dynsm);

    // ---- load all of W2 into SMEM (tf32), zero-pad cols 47..55
    for (int fid = tid; fid < G2_BELEMS; fid += 256) {
        int r = fid / G2_BSTRIDE;
        int c = fid - r * G2_BSTRIDE;
        float v = (c < NC) ? __ldg(B + (size_t)r * NC + c) : 0.f;
        Bw[fid] = f2tf32(v);
    }

    float acc[6][4];
#pragma unroll
    for (int ni = 0; ni < 6; ni++)
#pragma unroll
        for (int j = 0; j < 4; j++) acc[ni][j] = 0.f;

    const int NT = NH / 32;

    // A stage loader: 128 rows x 32 k = 1024 float4 -> 4 per thread
    auto load_stage = [&](int st, int k0) {
        uint32_t aBase = smem_u32 + (uint32_t)(st * G2_AELEMS) * 4u;
#pragma unroll
        for (int i = 0; i < 4; i++) {
            int fid = tid + i * 256;
            int r = fid >> 3, q = fid & 7;
            int gr = rowBase + r;
            bool ok = gr < NN;
            const float* src = g_a1 + (size_t)(ok ? gr : 0) * NH + k0 + q * 4;
            cp16(aBase + (uint32_t)(r * G2_ASTRIDE + q * 4) * 4u, src, ok);
        }
    };

    load_stage(0, 0);
    asm volatile("cp.async.commit_group;\n");

    for (int t = 0; t < NT; t++) {
        if (t + 1 < NT) load_stage((t + 1) & 1, (t + 1) * 32);
        asm volatile("cp.async.commit_group;\n");
        if (t + 1 < NT) asm volatile("cp.async.wait_group 1;\n");
        else            asm volatile("cp.async.wait_group 0;\n");
        __syncthreads();

        const uint32_t* AsS = dynsm + (t & 1) * G2_AELEMS;
        const int kbase = t * 32;

#pragma unroll
        for (int kk = 0; kk < 32; kk += 8) {
            uint32_t a[4];
            {
                int r0 = warpRow + gp;
                a[0] = f2tf32(__uint_as_float(AsS[r0 * G2_ASTRIDE + kk + tq]));
                a[1] = f2tf32(__uint_as_float(AsS[(r0 + 8) * G2_ASTRIDE + kk + tq]));
                a[2] = f2tf32(__uint_as_float(AsS[r0 * G2_ASTRIDE + kk + tq + 4]));
                a[3] = f2tf32(__uint_as_float(AsS[(r0 + 8) * G2_ASTRIDE + kk + tq + 4]));
            }
            uint32_t b[6][2];
#pragma unroll
            for (int ni = 0; ni < 6; ni++) {
                int c = ni * 8 + gp;                       // 0..47 < 56
                b[ni][0] = Bw[(kbase + kk + tq) * G2_BSTRIDE + c];
                b[ni][1] = Bw[(kbase + kk + tq + 4) * G2_BSTRIDE + c];
            }
#pragma unroll
            for (int ni = 0; ni < 6; ni++)
                mma_tf32(acc[ni][0], acc[ni][1], acc[ni][2], acc[ni][3],
                         a[0], a[1], a[2], a[3], b[ni][0], b[ni][1]);
        }
        __syncthreads();
    }

    // ---- epilogue with N guard (cols 0..46)
    {
        int r0 = rowBase + warpRow + gp;
        int r1 = r0 + 8;
        float d0 = (r0 < NN) ? g_dinv[r0] : 0.f;
        float d1 = (r1 < NN) ? g_dinv[r1] : 0.f;
#pragma unroll
        for (int ni = 0; ni < 6; ni++) {
            int c = ni * 8 + tq * 2;
            if (r0 < NN) {
                if (c < NC)     g_h2[(size_t)r0 * NC + c]     = d0 * acc[ni][0];
                if (c + 1 < NC) g_h2[(size_t)r0 * NC + c + 1] = d0 * acc[ni][1];
            }
            if (r1 < NN) {
                if (c < NC)     g_h2[(size_t)r1 * NC + c]     = d1 * acc[ni][2];
                if (c + 1 < NC) g_h2[(size_t)r1 * NC + c + 1] = d1 * acc[ni][3];
            }
        }
    }
}

// ---------------- agg2: out[i,c] = dinv[i]*sum_{adj} h2[row,c] + b2[c] ----------------
__global__ __launch_bounds__(256) void k_agg2(const float* __restrict__ b2,
                                              float* __restrict__ out) {
    int node = blockIdx.x * 8 + (threadIdx.x >> 5);
    if (node >= NN) return;
    int lane = threadIdx.x & 31;
    int s = g_offs[node], e = g_offs[node + 1];
    float a0 = 0.f, a1 = 0.f;
    for (int p = s; p < e; p++) {
        int r = g_adj[p];
        const float* gp = g_h2 + (size_t)r * NC;
        a0 += gp[lane];
        if (lane + 32 < NC) a1 += gp[lane + 32];
    }
    float d = g_dinv[node];
    out[(size_t)node * NC + lane] = d * a0 + b2[lane];
    if (lane + 32 < NC)
        out[(size_t)node * NC + lane + 32] = d * a1 + b2[lane + 32];
}

// ---------------- launch ----------------
extern "C" void kernel_launch(void* const* d_in, const int* in_sizes, int n_in,
                              void* d_out, int out_size) {
    const float* x  = (const float*)d_in[0];
    const int*   ei = (const int*)d_in[1];   // [2, NE] int32
    const float* W1 = (const float*)d_in[2];
    const float* b1 = (const float*)d_in[3];
    const float* W2 = (const float*)d_in[4];
    const float* b2 = (const float*)d_in[5];
    float* out = (float*)d_out;

    const int* erow = ei;
    const int* ecol = ei + NE;

    // graph prep
    k_init_deg<<<(NN + 255) / 256, 256>>>();
    k_count_deg<<<(NE + 255) / 256, 256>>>(ecol);
    int nsb = (NN + 511) / 512;  // 98
    k_scan_block<<<nsb, 512>>>();
    k_scan_bsum<<<1, 128>>>(nsb);
    k_scan_finish<<<(NN + 255) / 256, 256>>>();
    k_scatter<<<(NADJ + 255) / 256, 256>>>(erow, ecol);

    // layer 1 GEMM (pipelined TF32)
    cudaFuncSetAttribute(k_gemm1_tf32,
                         cudaFuncAttributeMaxDynamicSharedMemorySize, G1_SMEM_BYTES);
    dim3 g1(NH / 128, (NN + 127) / 128);
    k_gemm1_tf32<<<g1, 128, G1_SMEM_BYTES>>>(x, W1);

    // aggregation 1
    k_agg1<<<NN, 128>>>(b1);

    // layer 2 GEMM (W2-resident + pipelined A)
    cudaFuncSetAttribute(k_gemm2_tf32,
                         cudaFuncAttributeMaxDynamicSharedMemorySize, G2_SMEM_BYTES);
    k_gemm2_tf32<<<(NN + 127) / 128, 256, G2_SMEM_BYTES>>>(W2);

    // final aggregation
    k_agg2<<<(NN + 7) / 8, 256>>>(b2, out);
}

// round 9
// speedup vs baseline: 1.0108x; 1.0108x over previous
#include <cuda_runtime.h>
#include <cuda_bf16.h>
#include <cstdint>

// Problem constants
#define NN 50000
#define NE 150000
#define DF 512
#define NH 512
#define NC 47
#define NADJ (NE + NN)

// ---------------- scratch (static __device__ — no allocation) ----------------
__device__ int   g_deg[NN];
__device__ __align__(16) float g_dinv[NN];
__device__ int   g_incl[NN];
__device__ int   g_bsum[128];
__device__ int   g_offs[NN + 1];
__device__ int   g_cursor[NN];
__device__ int   g_adj[NADJ];
__device__ __align__(16) float g_h1[(size_t)NN * NH];   // dinv-scaled x@W1
__device__ __align__(16) float g_a1[(size_t)NN * NH];   // relu(agg1 + b1)
__device__ __align__(16) float g_h2[(size_t)NN * NC];   // dinv-scaled layer2 pre-agg

// ---------------- graph prep ----------------
__global__ void k_init_deg() {
    int i = blockIdx.x * blockDim.x + threadIdx.x;
    if (i < NN) g_deg[i] = 1;  // self loop
}

__global__ void k_count_deg(const int* __restrict__ ecol) {
    int e = blockIdx.x * blockDim.x + threadIdx.x;
    if (e < NE) atomicAdd(&g_deg[ecol[e]], 1);
}

__global__ void k_scan_block() {
    __shared__ int s[512];
    int i = blockIdx.x * 512 + threadIdx.x;
    int v = (i < NN) ? g_deg[i] : 0;
    s[threadIdx.x] = v;
    __syncthreads();
    for (int off = 1; off < 512; off <<= 1) {
        int t = (threadIdx.x >= off) ? s[threadIdx.x - off] : 0;
        __syncthreads();
        s[threadIdx.x] += t;
        __syncthreads();
    }
    if (i < NN) g_incl[i] = s[threadIdx.x];
    if (threadIdx.x == 511) g_bsum[blockIdx.x] = s[511];
}

// parallel exclusive scan of the 98 block sums (one 128-thread block)
__global__ void k_scan_bsum(int nblocks) {
    __shared__ int s[128];
    int t = threadIdx.x;
    int v = (t < nblocks) ? g_bsum[t] : 0;
    s[t] = v;
    __syncthreads();
    for (int off = 1; off < 128; off <<= 1) {
        int u = (t >= off) ? s[t - off] : 0;
        __syncthreads();
        s[t] += u;
        __syncthreads();
    }
    if (t < nblocks) g_bsum[t] = s[t] - v;  // exclusive
}

__global__ void k_scan_finish() {
    int i = blockIdx.x * blockDim.x + threadIdx.x;
    if (i < NN) {
        int e = g_incl[i] - g_deg[i] + g_bsum[i / 512];
        g_offs[i] = e;
        g_cursor[i] = e;
        g_dinv[i] = rsqrtf((float)g_deg[i]);
    }
    if (i == 0) g_offs[NN] = NADJ;
}

__global__ void k_scatter(const int* __restrict__ erow,
                          const int* __restrict__ ecol) {
    int t = blockIdx.x * blockDim.x + threadIdx.x;
    if (t < NE) {
        int c = ecol[t];
        int p = atomicAdd(&g_cursor[c], 1);
        g_adj[p] = erow[t];
    } else if (t < NADJ) {
        int i = t - NE;
        int p = atomicAdd(&g_cursor[i], 1);
        g_adj[p] = i;
    }
}

// ---------------- helpers ----------------
__device__ __forceinline__ uint32_t f2tf32(float f) {
    uint32_t u;
    asm("cvt.rna.tf32.f32 %0, %1;" : "=r"(u) : "f"(f));
    return u;
}

__device__ __forceinline__ void mma_tf32(float& c0, float& c1, float& c2, float& c3,
                                         uint32_t a0, uint32_t a1, uint32_t a2, uint32_t a3,
                                         uint32_t b0, uint32_t b1) {
    asm volatile(
        "mma.sync.aligned.m16n8k8.row.col.f32.tf32.tf32.f32 "
        "{%0,%1,%2,%3},{%4,%5,%6,%7},{%8,%9},{%0,%1,%2,%3};"
        : "+f"(c0), "+f"(c1), "+f"(c2), "+f"(c3)
        : "r"(a0), "r"(a1), "r"(a2), "r"(a3), "r"(b0), "r"(b1));
}

__device__ __forceinline__ void cp16(uint32_t dst_smem, const void* src, bool pred) {
    int sz = pred ? 16 : 0;
    asm volatile("cp.async.cg.shared.global [%0], [%1], 16, %2;\n"
                 :: "r"(dst_smem), "l"(src), "r"(sz));
}

// ---------------- GEMM1 (TF32, 2-stage cp.async pipeline) ----------------
// g_h1[m,f] = dinv[m] * sum_k x[m,k] * W1[k,f]
// BM=128, BN=256, BK=32; 256 threads = 8 warps (2M x 4N); warp tile 64x64.
#define G1_ASTRIDE 36
#define G1_BSTRIDE 264
#define G1_AELEMS (128 * G1_ASTRIDE)                 // 4608 words
#define G1_STAGE  (G1_AELEMS + 32 * G1_BSTRIDE)      // 13056 words
#define G1_SMEM_BYTES (2 * G1_STAGE * 4)             // 104448 B

__global__ __launch_bounds__(256) void k_gemm1_tf32(const float* __restrict__ A,
                                                    const float* __restrict__ B) {
    extern __shared__ __align__(16) uint32_t dynsm[];

    const int tid = threadIdx.x;
    const int lane = tid & 31;
    const int warp = tid >> 5;        // 0..7
    const int wm = warp & 1;
    const int wn = warp >> 1;         // 0..3
    const int gp = lane >> 2;
    const int tq = lane & 3;

    const int rowBase = blockIdx.y * 128;
    const int colBase = blockIdx.x * 256;
    const int warpRow = wm * 64;
    const int warpCol = wn * 64;

    uint32_t smem_u32 = (uint32_t)__cvta_generic_to_shared((void*)dynsm);

    float acc[4][8][4];
#pragma unroll
    for (int mi = 0; mi < 4; mi++)
#pragma unroll
        for (int ni = 0; ni < 8; ni++)
#pragma unroll
            for (int j = 0; j < 4; j++) acc[mi][ni][j] = 0.f;

    const int NT = DF / 32;  // 16 tiles

    auto load_stage = [&](int st, int k0) {
        uint32_t aBase = smem_u32 + (uint32_t)(st * G1_STAGE) * 4u;
        uint32_t bBase = aBase + (uint32_t)G1_AELEMS * 4u;
        // A: 128 rows x 32 k = 1024 float4 -> 4 per thread
#pragma unroll
        for (int i = 0; i < 4; i++) {
            int fid = tid + i * 256;
            int r = fid >> 3, q = fid & 7;
            int gr = rowBase + r;
            bool ok = gr < NN;
            const float* src = A + (size_t)(ok ? gr : 0) * DF + k0 + q * 4;
            cp16(aBase + (uint32_t)(r * G1_ASTRIDE + q * 4) * 4u, src, ok);
        }
        // B: 32 k-rows x 256 cols = 2048 float4 -> 8 per thread
#pragma unroll
        for (int i = 0; i < 8; i++) {
            int fid = tid + i * 256;
            int r = fid >> 6, q = fid & 63;
            const float* src = B + (size_t)(k0 + r) * NH + colBase + q * 4;
            cp16(bBase + (uint32_t)(r * G1_BSTRIDE + q * 4) * 4u, src, true);
        }
    };

    load_stage(0, 0);
    asm volatile("cp.async.commit_group;\n");

    for (int t = 0; t < NT; t++) {
        if (t + 1 < NT) load_stage((t + 1) & 1, (t + 1) * 32);
        asm volatile("cp.async.commit_group;\n");
        if (t + 1 < NT) asm volatile("cp.async.wait_group 1;\n");
        else            asm volatile("cp.async.wait_group 0;\n");
        __syncthreads();

        const uint32_t* AsS = dynsm + (t & 1) * G1_STAGE;
        const uint32_t* BsS = AsS + G1_AELEMS;

#pragma unroll
        for (int kk = 0; kk < 32; kk += 8) {
            uint32_t a[4][4];
#pragma unroll
            for (int mi = 0; mi < 4; mi++) {
                int r0 = warpRow + mi * 16 + gp;
                a[mi][0] = f2tf32(__uint_as_float(AsS[r0 * G1_ASTRIDE + kk + tq]));
                a[mi][1] = f2tf32(__uint_as_float(AsS[(r0 + 8) * G1_ASTRIDE + kk + tq]));
                a[mi][2] = f2tf32(__uint_as_float(AsS[r0 * G1_ASTRIDE + kk + tq + 4]));
                a[mi][3] = f2tf32(__uint_as_float(AsS[(r0 + 8) * G1_ASTRIDE + kk + tq + 4]));
            }
            uint32_t b[8][2];
#pragma unroll
            for (int ni = 0; ni < 8; ni++) {
                int c = warpCol + ni * 8 + gp;
                b[ni][0] = f2tf32(__uint_as_float(BsS[(kk + tq) * G1_BSTRIDE + c]));
                b[ni][1] = f2tf32(__uint_as_float(BsS[(kk + tq + 4) * G1_BSTRIDE + c]));
            }
#pragma unroll
            for (int mi = 0; mi < 4; mi++)
#pragma unroll
                for (int ni = 0; ni < 8; ni++)
                    mma_tf32(acc[mi][ni][0], acc[mi][ni][1],
                             acc[mi][ni][2], acc[mi][ni][3],
                             a[mi][0], a[mi][1], a[mi][2], a[mi][3],
                             b[ni][0], b[ni][1]);
        }
        __syncthreads();
    }

#pragma unroll
    for (int mi = 0; mi < 4; mi++) {
        int r0 = rowBase + warpRow + mi * 16 + gp;
        int r1 = r0 + 8;
        float d0 = (r0 < NN) ? g_dinv[r0] : 0.f;
        float d1 = (r1 < NN) ? g_dinv[r1] : 0.f;
#pragma unroll
        for (int ni = 0; ni < 8; ni++) {
            int c = colBase + warpCol + ni * 8 + tq * 2;
            if (r0 < NN) {
                float2 o = make_float2(d0 * acc[mi][ni][0], d0 * acc[mi][ni][1]);
                *(float2*)(g_h1 + (size_t)r0 * NH + c) = o;
            }
            if (r1 < NN) {
                float2 o = make_float2(d1 * acc[mi][ni][2], d1 * acc[mi][ni][3]);
                *(float2*)(g_h1 + (size_t)r1 * NH + c) = o;
            }
        }
    }
}

// ---------------- agg1: a1[i,f] = relu(dinv[i]*sum_{adj} h1[row,f] + b1[f]) ----------------
__global__ __launch_bounds__(128) void k_agg1(const float* __restrict__ b1) {
    const int node = blockIdx.x;
    const int f = threadIdx.x * 4;
    const int s = g_offs[node], e = g_offs[node + 1];
    float4 acc = make_float4(0.f, 0.f, 0.f, 0.f);
    for (int p = s; p < e; p++) {
        int r = g_adj[p];
        float4 v = *(const float4*)(g_h1 + (size_t)r * NH + f);
        acc.x += v.x; acc.y += v.y; acc.z += v.z; acc.w += v.w;
    }
    float d = g_dinv[node];
    float4 bb = *(const float4*)(b1 + f);
    float4 o;
    o.x = fmaxf(d * acc.x + bb.x, 0.f);
    o.y = fmaxf(d * acc.y + bb.y, 0.f);
    o.z = fmaxf(d * acc.z + bb.z, 0.f);
    o.w = fmaxf(d * acc.w + bb.w, 0.f);
    *(float4*)(g_a1 + (size_t)node * NH + f) = o;
}

// ---------------- GEMM2 (TF32): g_h2[m,c] = dinv[m] * sum_k a1[m,k] * W2[k,c] ----------------
// BM=128, BN=64 (covers 47 with guard), BK=32; 256 threads = 8 warps (4M x 2N); warp tile 32x32.
// (R6 version — known good.)
__global__ __launch_bounds__(256) void k_gemm2_tf32(const float* __restrict__ B) {
    __shared__ __align__(16) uint32_t As[128][36];
    __shared__ __align__(16) uint32_t Bs[32][72];    // pad72: b-frag conflict-free

    const int tid = threadIdx.x;
    const int lane = tid & 31;
    const int warp = tid >> 5;        // 0..7
    const int wm = warp & 3;
    const int wn = warp >> 2;
    const int gp = lane >> 2;
    const int tq = lane & 3;

    const int rowBase = blockIdx.x * 128;
    const int warpRow = wm * 32;
    const int warpCol = wn * 32;

    float acc[2][4][4];
#pragma unroll
    for (int mi = 0; mi < 2; mi++)
#pragma unroll
        for (int ni = 0; ni < 4; ni++)
#pragma unroll
            for (int j = 0; j < 4; j++) acc[mi][ni][j] = 0.f;

    for (int k0 = 0; k0 < NH; k0 += 32) {
#pragma unroll
        for (int i = 0; i < 4; i++) {
            int fid = tid + i * 256;
            int r = fid >> 3, q = fid & 7;
            int gr = rowBase + r;
            float4 v = make_float4(0.f, 0.f, 0.f, 0.f);
            if (gr < NN) v = __ldg((const float4*)(g_a1 + (size_t)gr * NH + k0 + q * 4));
            uint4 u;
            u.x = f2tf32(v.x); u.y = f2tf32(v.y);
            u.z = f2tf32(v.z); u.w = f2tf32(v.w);
            *(uint4*)(&As[r][q * 4]) = u;
        }
#pragma unroll
        for (int i = 0; i < 8; i++) {
            int fid = tid + i * 256;
            int r = fid >> 6, c = fid & 63;
            float v = (c < NC) ? __ldg(B + (size_t)(k0 + r) * NC + c) : 0.f;
            Bs[r][c] = f2tf32(v);
        }
        __syncthreads();

#pragma unroll
        for (int kk = 0; kk < 32; kk += 8) {
            uint32_t a[2][4];
#pragma unroll
            for (int mi = 0; mi < 2; mi++) {
                int r0 = warpRow + mi * 16 + gp;
                a[mi][0] = As[r0][kk + tq];
                a[mi][1] = As[r0 + 8][kk + tq];
                a[mi][2] = As[r0][kk + tq + 4];
                a[mi][3] = As[r0 + 8][kk + tq + 4];
            }
            uint32_t b[4][2];
#pragma unroll
            for (int ni = 0; ni < 4; ni++) {
                int c = warpCol + ni * 8 + gp;
                b[ni][0] = Bs[kk + tq][c];
                b[ni][1] = Bs[kk + tq + 4][c];
            }
#pragma unroll
            for (int mi = 0; mi < 2; mi++)
#pragma unroll
                for (int ni = 0; ni < 4; ni++)
                    mma_tf32(acc[mi][ni][0], acc[mi][ni][1],
                             acc[mi][ni][2], acc[mi][ni][3],
                             a[mi][0], a[mi][1], a[mi][2], a[mi][3],
                             b[ni][0], b[ni][1]);
        }
        __syncthreads();
    }

#pragma unroll
    for (int mi = 0; mi < 2; mi++) {
        int r0 = rowBase + warpRow + mi * 16 + gp;
        int r1 = r0 + 8;
        float d0 = (r0 < NN) ? g_dinv[r0] : 0.f;
        float d1 = (r1 < NN) ? g_dinv[r1] : 0.f;
#pragma unroll
        for (int ni = 0; ni < 4; ni++) {
            int c = warpCol + ni * 8 + tq * 2;
            if (r0 < NN) {
                if (c < NC)     g_h2[(size_t)r0 * NC + c]     = d0 * acc[mi][ni][0];
                if (c + 1 < NC) g_h2[(size_t)r0 * NC + c + 1] = d0 * acc[mi][ni][1];
            }
            if (r1 < NN) {
                if (c < NC)     g_h2[(size_t)r1 * NC + c]     = d1 * acc[mi][ni][2];
                if (c + 1 < NC) g_h2[(size_t)r1 * NC + c + 1] = d1 * acc[mi][ni][3];
            }
        }
    }
}

// ---------------- agg2: out[i,c] = dinv[i]*sum_{adj} h2[row,c] + b2[c] ----------------
__global__ __launch_bounds__(256) void k_agg2(const float* __restrict__ b2,
                                              float* __restrict__ out) {
    int node = blockIdx.x * 8 + (threadIdx.x >> 5);
    if (node >= NN) return;
    int lane = threadIdx.x & 31;
    int s = g_offs[node], e = g_offs[node + 1];
    float a0 = 0.f, a1 = 0.f;
    for (int p = s; p < e; p++) {
        int r = g_adj[p];
        const float* gp = g_h2 + (size_t)r * NC;
        a0 += gp[lane];
        if (lane + 32 < NC) a1 += gp[lane + 32];
    }
    float d = g_dinv[node];
    out[(size_t)node * NC + lane] = d * a0 + b2[lane];
    if (lane + 32 < NC)
        out[(size_t)node * NC + lane + 32] = d * a1 + b2[lane + 32];
}

// ---------------- launch ----------------
extern "C" void kernel_launch(void* const* d_in, const int* in_sizes, int n_in,
                              void* d_out, int out_size) {
    const float* x  = (const float*)d_in[0];
    const int*   ei = (const int*)d_in[1];   // [2, NE] int32
    const float* W1 = (const float*)d_in[2];
    const float* b1 = (const float*)d_in[3];
    const float* W2 = (const float*)d_in[4];
    const float* b2 = (const float*)d_in[5];
    float* out = (float*)d_out;

    const int* erow = ei;
    const int* ecol = ei + NE;

    // graph prep
    k_init_deg<<<(NN + 255) / 256, 256>>>();
    k_count_deg<<<(NE + 255) / 256, 256>>>(ecol);
    int nsb = (NN + 511) / 512;  // 98
    k_scan_block<<<nsb, 512>>>();
    k_scan_bsum<<<1, 128>>>(nsb);
    k_scan_finish<<<(NN + 255) / 256, 256>>>();
    k_scatter<<<(NADJ + 255) / 256, 256>>>(erow, ecol);

    // layer 1 GEMM (pipelined TF32, BN=256)
    cudaFuncSetAttribute(k_gemm1_tf32,
                         cudaFuncAttributeMaxDynamicSharedMemorySize, G1_SMEM_BYTES);
    dim3 g1(NH / 256, (NN + 127) / 128);
    k_gemm1_tf32<<<g1, 256, G1_SMEM_BYTES>>>(x, W1);

    // aggregation 1
    k_agg1<<<NN, 128>>>(b1);

    // layer 2 GEMM (R6 version)
    k_gemm2_tf32<<<(NN + 127) / 128, 256>>>(W2);

    // final aggregation
    k_agg2<<<(NN + 7) / 8, 256>>>(b2, out);
}

// round 10
// speedup vs baseline: 1.1288x; 1.1167x over previous
#include <cuda_runtime.h>
#include <cuda_bf16.h>
#include <cstdint>

// Problem constants
#define NN 50000
#define NE 150000
#define DF 512
#define NH 512
#define NC 47
#define NADJ (NE + NN)

// ---------------- scratch (static __device__ — no allocation) ----------------
__device__ int   g_deg[NN];
__device__ __align__(16) float g_dinv[NN];
__device__ int   g_incl[NN];
__device__ int   g_bsum[128];
__device__ int   g_offs[NN + 1];
__device__ int   g_cursor[NN];
__device__ int   g_adj[NADJ];
__device__ __align__(16) float g_h1[(size_t)NN * NH];   // dinv-scaled x@W1
__device__ __align__(16) float g_a1[(size_t)NN * NH];   // relu(agg1 + b1)
__device__ __align__(16) float g_h2[(size_t)NN * NC];   // dinv-scaled layer2 pre-agg

// ---------------- graph prep ----------------
__global__ void k_init_deg() {
    int i = blockIdx.x * blockDim.x + threadIdx.x;
    if (i < NN) g_deg[i] = 1;  // self loop
}

__global__ void k_count_deg(const int* __restrict__ ecol) {
    int e = blockIdx.x * blockDim.x + threadIdx.x;
    if (e < NE) atomicAdd(&g_deg[ecol[e]], 1);
}

__global__ void k_scan_block() {
    __shared__ int s[512];
    int i = blockIdx.x * 512 + threadIdx.x;
    int v = (i < NN) ? g_deg[i] : 0;
    s[threadIdx.x] = v;
    __syncthreads();
    for (int off = 1; off < 512; off <<= 1) {
        int t = (threadIdx.x >= off) ? s[threadIdx.x - off] : 0;
        __syncthreads();
        s[threadIdx.x] += t;
        __syncthreads();
    }
    if (i < NN) g_incl[i] = s[threadIdx.x];
    if (threadIdx.x == 511) g_bsum[blockIdx.x] = s[511];
}

// parallel exclusive scan of the 98 block sums (one 128-thread block)
__global__ void k_scan_bsum(int nblocks) {
    __shared__ int s[128];
    int t = threadIdx.x;
    int v = (t < nblocks) ? g_bsum[t] : 0;
    s[t] = v;
    __syncthreads();
    for (int off = 1; off < 128; off <<= 1) {
        int u = (t >= off) ? s[t - off] : 0;
        __syncthreads();
        s[t] += u;
        __syncthreads();
    }
    if (t < nblocks) g_bsum[t] = s[t] - v;  // exclusive
}

__global__ void k_scan_finish() {
    int i = blockIdx.x * blockDim.x + threadIdx.x;
    if (i < NN) {
        int e = g_incl[i] - g_deg[i] + g_bsum[i / 512];
        g_offs[i] = e;
        g_cursor[i] = e;
        g_dinv[i] = rsqrtf((float)g_deg[i]);
    }
    if (i == 0) g_offs[NN] = NADJ;
}

__global__ void k_scatter(const int* __restrict__ erow,
                          const int* __restrict__ ecol) {
    int t = blockIdx.x * blockDim.x + threadIdx.x;
    if (t < NE) {
        int c = ecol[t];
        int p = atomicAdd(&g_cursor[c], 1);
        g_adj[p] = erow[t];
    } else if (t < NADJ) {
        int i = t - NE;
        int p = atomicAdd(&g_cursor[i], 1);
        g_adj[p] = i;
    }
}

// ---------------- helpers ----------------
__device__ __forceinline__ uint32_t f2tf32(float f) {
    uint32_t u;
    asm("cvt.rna.tf32.f32 %0, %1;" : "=r"(u) : "f"(f));
    return u;
}

__device__ __forceinline__ void mma_tf32(float& c0, float& c1, float& c2, float& c3,
                                         uint32_t a0, uint32_t a1, uint32_t a2, uint32_t a3,
                                         uint32_t b0, uint32_t b1) {
    asm volatile(
        "mma.sync.aligned.m16n8k8.row.col.f32.tf32.tf32.f32 "
        "{%0,%1,%2,%3},{%4,%5,%6,%7},{%8,%9},{%0,%1,%2,%3};"
        : "+f"(c0), "+f"(c1), "+f"(c2), "+f"(c3)
        : "r"(a0), "r"(a1), "r"(a2), "r"(a3), "r"(b0), "r"(b1));
}

__device__ __forceinline__ void cp16(uint32_t dst_smem, const void* src, bool pred) {
    int sz = pred ? 16 : 0;
    asm volatile("cp.async.cg.shared.global [%0], [%1], 16, %2;\n"
                 :: "r"(dst_smem), "l"(src), "r"(sz));
}

// ---------------- GEMM1 (TF32, 2-stage cp.async pipeline) — R6 known-good --------
// g_h1[m,f] = dinv[m] * sum_k x[m,k] * W1[k,f]
// BM=128, BN=128, BK=32; 128 threads = 4 warps (2M x 2N); warp tile 64x64.
#define G1_ASTRIDE 36
#define G1_BSTRIDE 136
#define G1_AELEMS (128 * G1_ASTRIDE)
#define G1_STAGE  (G1_AELEMS + 32 * G1_BSTRIDE)
#define G1_SMEM_BYTES (2 * G1_STAGE * 4)

__global__ __launch_bounds__(128) void k_gemm1_tf32(const float* __restrict__ A,
                                                    const float* __restrict__ B) {
    extern __shared__ __align__(16) uint32_t dynsm[];

    const int tid = threadIdx.x;
    const int lane = tid & 31;
    const int warp = tid >> 5;
    const int wm = warp & 1;
    const int wn = warp >> 1;
    const int gp = lane >> 2;
    const int tq = lane & 3;

    const int rowBase = blockIdx.y * 128;
    const int colBase = blockIdx.x * 128;
    const int warpRow = wm * 64;
    const int warpCol = wn * 64;

    uint32_t smem_u32 = (uint32_t)__cvta_generic_to_shared((void*)dynsm);

    float acc[4][8][4];
#pragma unroll
    for (int mi = 0; mi < 4; mi++)
#pragma unroll
        for (int ni = 0; ni < 8; ni++)
#pragma unroll
            for (int j = 0; j < 4; j++) acc[mi][ni][j] = 0.f;

    const int NT = DF / 32;

    auto load_stage = [&](int st, int k0) {
        uint32_t aBase = smem_u32 + (uint32_t)(st * G1_STAGE) * 4u;
        uint32_t bBase = aBase + (uint32_t)G1_AELEMS * 4u;
#pragma unroll
        for (int i = 0; i < 8; i++) {
            int fid = tid + i * 128;
            int r = fid >> 3, q = fid & 7;
            int gr = rowBase + r;
            bool ok = gr < NN;
            const float* src = A + (size_t)(ok ? gr : 0) * DF + k0 + q * 4;
            cp16(aBase + (uint32_t)(r * G1_ASTRIDE + q * 4) * 4u, src, ok);
        }
#pragma unroll
        for (int i = 0; i < 8; i++) {
            int fid = tid + i * 128;
            int r = fid >> 5, q = fid & 31;
            const float* src = B + (size_t)(k0 + r) * NH + colBase + q * 4;
            cp16(bBase + (uint32_t)(r * G1_BSTRIDE + q * 4) * 4u, src, true);
        }
    };

    load_stage(0, 0);
    asm volatile("cp.async.commit_group;\n");

    for (int t = 0; t < NT; t++) {
        if (t + 1 < NT) load_stage((t + 1) & 1, (t + 1) * 32);
        asm volatile("cp.async.commit_group;\n");
        if (t + 1 < NT) asm volatile("cp.async.wait_group 1;\n");
        else            asm volatile("cp.async.wait_group 0;\n");
        __syncthreads();

        const uint32_t* AsS = dynsm + (t & 1) * G1_STAGE;
        const uint32_t* BsS = AsS + G1_AELEMS;

#pragma unroll
        for (int kk = 0; kk < 32; kk += 8) {
            uint32_t a[4][4];
#pragma unroll
            for (int mi = 0; mi < 4; mi++) {
                int r0 = warpRow + mi * 16 + gp;
                a[mi][0] = f2tf32(__uint_as_float(AsS[r0 * G1_ASTRIDE + kk + tq]));
                a[mi][1] = f2tf32(__uint_as_float(AsS[(r0 + 8) * G1_ASTRIDE + kk + tq]));
                a[mi][2] = f2tf32(__uint_as_float(AsS[r0 * G1_ASTRIDE + kk + tq + 4]));
                a[mi][3] = f2tf32(__uint_as_float(AsS[(r0 + 8) * G1_ASTRIDE + kk + tq + 4]));
            }
            uint32_t b[8][2];
#pragma unroll
            for (int ni = 0; ni < 8; ni++) {
                int c = warpCol + ni * 8 + gp;
                b[ni][0] = f2tf32(__uint_as_float(BsS[(kk + tq) * G1_BSTRIDE + c]));
                b[ni][1] = f2tf32(__uint_as_float(BsS[(kk + tq + 4) * G1_BSTRIDE + c]));
            }
#pragma unroll
            for (int mi = 0; mi < 4; mi++)
#pragma unroll
                for (int ni = 0; ni < 8; ni++)
                    mma_tf32(acc[mi][ni][0], acc[mi][ni][1],
                             acc[mi][ni][2], acc[mi][ni][3],
                             a[mi][0], a[mi][1], a[mi][2], a[mi][3],
                             b[ni][0], b[ni][1]);
        }
        __syncthreads();
    }

#pragma unroll
    for (int mi = 0; mi < 4; mi++) {
        int r0 = rowBase + warpRow + mi * 16 + gp;
        int r1 = r0 + 8;
        float d0 = (r0 < NN) ? g_dinv[r0] : 0.f;
        float d1 = (r1 < NN) ? g_dinv[r1] : 0.f;
#pragma unroll
        for (int ni = 0; ni < 8; ni++) {
            int c = colBase + warpCol + ni * 8 + tq * 2;
            if (r0 < NN) {
                float2 o = make_float2(d0 * acc[mi][ni][0], d0 * acc[mi][ni][1]);
                *(float2*)(g_h1 + (size_t)r0 * NH + c) = o;
            }
            if (r1 < NN) {
                float2 o = make_float2(d1 * acc[mi][ni][2], d1 * acc[mi][ni][3]);
                *(float2*)(g_h1 + (size_t)r1 * NH + c) = o;
            }
        }
    }
}

// ---------------- agg1: a1[i,f] = relu(dinv[i]*sum_{adj} h1[row,f] + b1[f]) ----------------
__global__ __launch_bounds__(128) void k_agg1(const float* __restrict__ b1) {
    const int node = blockIdx.x;
    const int f = threadIdx.x * 4;
    const int s = g_offs[node], e = g_offs[node + 1];
    float4 acc = make_float4(0.f, 0.f, 0.f, 0.f);
    for (int p = s; p < e; p++) {
        int r = g_adj[p];
        float4 v = *(const float4*)(g_h1 + (size_t)r * NH + f);
        acc.x += v.x; acc.y += v.y; acc.z += v.z; acc.w += v.w;
    }
    float d = g_dinv[node];
    float4 bb = *(const float4*)(b1 + f);
    float4 o;
    o.x = fmaxf(d * acc.x + bb.x, 0.f);
    o.y = fmaxf(d * acc.y + bb.y, 0.f);
    o.z = fmaxf(d * acc.z + bb.z, 0.f);
    o.w = fmaxf(d * acc.w + bb.w, 0.f);
    *(float4*)(g_a1 + (size_t)node * NH + f) = o;
}

// ---------------- GEMM2 (TF32, 2-stage cp.async A pipeline) ----------------
// g_h2[m,c] = dinv[m] * sum_k a1[m,k] * W2[k,c]
// BM=128, BN=64 (guarded to 47), BK=32; 256 threads = 8 warps (4M x 2N); warp tile 32x32.
__global__ __launch_bounds__(256) void k_gemm2_tf32(const float* __restrict__ B) {
    __shared__ __align__(16) uint32_t Asr[2][128][36];   // raw fp32 bits, double-buffered
    __shared__ __align__(16) uint32_t Bs[32][72];        // tf32, pad72 conflict-free

    const int tid = threadIdx.x;
    const int lane = tid & 31;
    const int warp = tid >> 5;        // 0..7
    const int wm = warp & 3;
    const int wn = warp >> 2;
    const int gp = lane >> 2;
    const int tq = lane & 3;

    const int rowBase = blockIdx.x * 128;
    const int warpRow = wm * 32;
    const int warpCol = wn * 32;

    uint32_t aSm = (uint32_t)__cvta_generic_to_shared((void*)&Asr[0][0][0]);

    float acc[2][4][4];
#pragma unroll
    for (int mi = 0; mi < 2; mi++)
#pragma unroll
        for (int ni = 0; ni < 4; ni++)
#pragma unroll
            for (int j = 0; j < 4; j++) acc[mi][ni][j] = 0.f;

    const int NT = NH / 32;  // 16

    // A stage loader: 128 rows x 32 k = 1024 float4 -> 4 per thread
    auto load_stage = [&](int st, int k0) {
        uint32_t aBase = aSm + (uint32_t)(st * 128 * 36) * 4u;
#pragma unroll
        for (int i = 0; i < 4; i++) {
            int fid = tid + i * 256;
            int r = fid >> 3, q = fid & 7;
            int gr = rowBase + r;
            bool ok = gr < NN;
            const float* src = g_a1 + (size_t)(ok ? gr : 0) * NH + k0 + q * 4;
            cp16(aBase + (uint32_t)(r * 36 + q * 4) * 4u, src, ok);
        }
    };

    load_stage(0, 0);
    asm volatile("cp.async.commit_group;\n");

    for (int t = 0; t < NT; t++) {
        if (t + 1 < NT) load_stage((t + 1) & 1, (t + 1) * 32);
        asm volatile("cp.async.commit_group;\n");

        // B tile (synchronous; Bs write-after-read protected by loop-end sync)
#pragma unroll
        for (int i = 0; i < 8; i++) {
            int fid = tid + i * 256;
            int r = fid >> 6, c = fid & 63;
            float v = (c < NC) ? __ldg(B + (size_t)(t * 32 + r) * NC + c) : 0.f;
            if (c < 72) Bs[r][c] = f2tf32(v);
        }

        if (t + 1 < NT) asm volatile("cp.async.wait_group 1;\n");
        else            asm volatile("cp.async.wait_group 0;\n");
        __syncthreads();

        const uint32_t (*AsS)[36] = Asr[t & 1];

#pragma unroll
        for (int kk = 0; kk < 32; kk += 8) {
            uint32_t a[2][4];
#pragma unroll
            for (int mi = 0; mi < 2; mi++) {
                int r0 = warpRow + mi * 16 + gp;
                a[mi][0] = f2tf32(__uint_as_float(AsS[r0][kk + tq]));
                a[mi][1] = f2tf32(__uint_as_float(AsS[r0 + 8][kk + tq]));
                a[mi][2] = f2tf32(__uint_as_float(AsS[r0][kk + tq + 4]));
                a[mi][3] = f2tf32(__uint_as_float(AsS[r0 + 8][kk + tq + 4]));
            }
            uint32_t b[4][2];
#pragma unroll
            for (int ni = 0; ni < 4; ni++) {
                int c = warpCol + ni * 8 + gp;
                b[ni][0] = Bs[kk + tq][c];
                b[ni][1] = Bs[kk + tq + 4][c];
            }
#pragma unroll
            for (int mi = 0; mi < 2; mi++)
#pragma unroll
                for (int ni = 0; ni < 4; ni++)
                    mma_tf32(acc[mi][ni][0], acc[mi][ni][1],
                             acc[mi][ni][2], acc[mi][ni][3],
                             a[mi][0], a[mi][1], a[mi][2], a[mi][3],
                             b[ni][0], b[ni][1]);
        }
        __syncthreads();
    }

    // ---- epilogue with N guard
#pragma unroll
    for (int mi = 0; mi < 2; mi++) {
        int r0 = rowBase + warpRow + mi * 16 + gp;
        int r1 = r0 + 8;
        float d0 = (r0 < NN) ? g_dinv[r0] : 0.f;
        float d1 = (r1 < NN) ? g_dinv[r1] : 0.f;
#pragma unroll
        for (int ni = 0; ni < 4; ni++) {
            int c = warpCol + ni * 8 + tq * 2;
            if (r0 < NN) {
                if (c < NC)     g_h2[(size_t)r0 * NC + c]     = d0 * acc[mi][ni][0];
                if (c + 1 < NC) g_h2[(size_t)r0 * NC + c + 1] = d0 * acc[mi][ni][1];
            }
            if (r1 < NN) {
                if (c < NC)     g_h2[(size_t)r1 * NC + c]     = d1 * acc[mi][ni][2];
                if (c + 1 < NC) g_h2[(size_t)r1 * NC + c + 1] = d1 * acc[mi][ni][3];
            }
        }
    }
}

// ---------------- agg2: out[i,c] = dinv[i]*sum_{adj} h2[row,c] + b2[c] ----------------
__global__ __launch_bounds__(256) void k_agg2(const float* __restrict__ b2,
                                              float* __restrict__ out) {
    int node = blockIdx.x * 8 + (threadIdx.x >> 5);
    if (node >= NN) return;
    int lane = threadIdx.x & 31;
    int s = g_offs[node], e = g_offs[node + 1];
    float a0 = 0.f, a1 = 0.f;
    for (int p = s; p < e; p++) {
        int r = g_adj[p];
        const float* gp = g_h2 + (size_t)r * NC;
        a0 += gp[lane];
        if (lane + 32 < NC) a1 += gp[lane + 32];
    }
    float d = g_dinv[node];
    out[(size_t)node * NC + lane] = d * a0 + b2[lane];
    if (lane + 32 < NC)
        out[(size_t)node * NC + lane + 32] = d * a1 + b2[lane + 32];
}

// ---------------- launch ----------------
extern "C" void kernel_launch(void* const* d_in, const int* in_sizes, int n_in,
                              void* d_out, int out_size) {
    const float* x  = (const float*)d_in[0];
    const int*   ei = (const int*)d_in[1];   // [2, NE] int32
    const float* W1 = (const float*)d_in[2];
    const float* b1 = (const float*)d_in[3];
    const float* W2 = (const float*)d_in[4];
    const float* b2 = (const float*)d_in[5];
    float* out = (float*)d_out;

    const int* erow = ei;
    const int* ecol = ei + NE;

    // graph prep
    k_init_deg<<<(NN + 255) / 256, 256>>>();
    k_count_deg<<<(NE + 255) / 256, 256>>>(ecol);
    int nsb = (NN + 511) / 512;  // 98
    k_scan_block<<<nsb, 512>>>();
    k_scan_bsum<<<1, 128>>>(nsb);
    k_scan_finish<<<(NN + 255) / 256, 256>>>();
    k_scatter<<<(NADJ + 255) / 256, 256>>>(erow, ecol);

    // layer 1 GEMM (pipelined TF32, R6 config)
    cudaFuncSetAttribute(k_gemm1_tf32,
                         cudaFuncAttributeMaxDynamicSharedMemorySize, G1_SMEM_BYTES);
    dim3 g1(NH / 128, (NN + 127) / 128);
    k_gemm1_tf32<<<g1, 128, G1_SMEM_BYTES>>>(x, W1);

    // aggregation 1
    k_agg1<<<NN, 128>>>(b1);

    // layer 2 GEMM (pipelined A)
    k_gemm2_tf32<<<(NN + 127) / 128, 256>>>(W2);

    // final aggregation
    k_agg2<<<(NN + 7) / 8, 256>>>(b2, out);
}

// round 11
// speedup vs baseline: 1.1648x; 1.0319x over previous
#include <cuda_runtime.h>
#include <cuda_bf16.h>
#include <cstdint>

// Problem constants
#define NN 50000
#define NE 150000
#define DF 512
#define NH 512
#define NC 47
#define NADJ (NE + NN)
#define NSB 98   // (NN+511)/512

// ---------------- scratch (static __device__ — no allocation) ----------------
__device__ int   g_deg[NN];
__device__ __align__(16) float g_dinv[NN];
__device__ int   g_incl[NN];
__device__ int   g_bsum[128];
__device__ int   g_offs[NN + 1];
__device__ int   g_cursor[NN];
__device__ int   g_adj[NADJ];
__device__ __align__(16) float g_h1[(size_t)NN * NH];   // RAW x@W1 (no dinv)
__device__ __align__(16) float g_a1[(size_t)NN * NH];   // relu(agg1 + b1)
__device__ __align__(16) float g_h2[(size_t)NN * NC];   // dinv-scaled layer2 pre-agg

// ---------------- graph prep ----------------
__global__ void k_init_deg() {
    int i = blockIdx.x * blockDim.x + threadIdx.x;
    if (i < NN) g_deg[i] = 1;  // self loop
}

__global__ void k_count_deg(const int* __restrict__ ecol) {
    int e = blockIdx.x * blockDim.x + threadIdx.x;
    if (e < NE) atomicAdd(&g_deg[ecol[e]], 1);
}

__global__ void k_scan_block() {
    __shared__ int s[512];
    int i = blockIdx.x * 512 + threadIdx.x;
    int v = (i < NN) ? g_deg[i] : 0;
    s[threadIdx.x] = v;
    __syncthreads();
    for (int off = 1; off < 512; off <<= 1) {
        int t = (threadIdx.x >= off) ? s[threadIdx.x - off] : 0;
        __syncthreads();
        s[threadIdx.x] += t;
        __syncthreads();
    }
    if (i < NN) g_incl[i] = s[threadIdx.x];
    if (threadIdx.x == 511) g_bsum[blockIdx.x] = s[511];  // raw block total
}

// finish: inline (redundant per-block) exclusive scan of the 98 block sums
__global__ void k_scan_finish2() {
    __shared__ int sx[128];
    int t = threadIdx.x;
    int v = 0;
    if (t < 128) { v = (t < NSB) ? g_bsum[t] : 0; sx[t] = v; }
    __syncthreads();
    for (int off = 1; off < 128; off <<= 1) {
        int u = 0;
        if (t < 128 && t >= off) u = sx[t - off];
        __syncthreads();
        if (t < 128) sx[t] += u;
        __syncthreads();
    }
    if (t < 128) sx[t] -= v;   // exclusive
    __syncthreads();
    int i = blockIdx.x * blockDim.x + t;
    if (i < NN) {
        int e = g_incl[i] - g_deg[i] + sx[i >> 9];
        g_offs[i] = e;
        g_cursor[i] = e;
        g_dinv[i] = rsqrtf((float)g_deg[i]);
    }
    if (i == 0) g_offs[NN] = NADJ;
}

__global__ void k_scatter(const int* __restrict__ erow,
                          const int* __restrict__ ecol) {
    int t = blockIdx.x * blockDim.x + threadIdx.x;
    if (t < NE) {
        int c = ecol[t];
        int p = atomicAdd(&g_cursor[c], 1);
        g_adj[p] = erow[t];
    } else if (t < NADJ) {
        int i = t - NE;
        int p = atomicAdd(&g_cursor[i], 1);
        g_adj[p] = i;
    }
}

// ---------------- helpers ----------------
__device__ __forceinline__ uint32_t f2tf32(float f) {
    uint32_t u;
    asm("cvt.rna.tf32.f32 %0, %1;" : "=r"(u) : "f"(f));
    return u;
}

__device__ __forceinline__ void mma_tf32(float& c0, float& c1, float& c2, float& c3,
                                         uint32_t a0, uint32_t a1, uint32_t a2, uint32_t a3,
                                         uint32_t b0, uint32_t b1) {
    asm volatile(
        "mma.sync.aligned.m16n8k8.row.col.f32.tf32.tf32.f32 "
        "{%0,%1,%2,%3},{%4,%5,%6,%7},{%8,%9},{%0,%1,%2,%3};"
        : "+f"(c0), "+f"(c1), "+f"(c2), "+f"(c3)
        : "r"(a0), "r"(a1), "r"(a2), "r"(a3), "r"(b0), "r"(b1));
}

__device__ __forceinline__ void cp16(uint32_t dst_smem, const void* src, bool pred) {
    int sz = pred ? 16 : 0;
    asm volatile("cp.async.cg.shared.global [%0], [%1], 16, %2;\n"
                 :: "r"(dst_smem), "l"(src), "r"(sz));
}

// ---------------- GEMM1 (TF32, 2-stage cp.async pipeline) ----------------
// g_h1[m,f] = sum_k x[m,k] * W1[k,f]   (RAW — dinv applied in agg1)
// BM=128, BN=128, BK=32; 128 threads = 4 warps (2M x 2N); warp tile 64x64.
#define G1_ASTRIDE 36
#define G1_BSTRIDE 136
#define G1_AELEMS (128 * G1_ASTRIDE)
#define G1_STAGE  (G1_AELEMS + 32 * G1_BSTRIDE)
#define G1_SMEM_BYTES (2 * G1_STAGE * 4)

__global__ __launch_bounds__(128) void k_gemm1_tf32(const float* __restrict__ A,
                                                    const float* __restrict__ B) {
    extern __shared__ __align__(16) uint32_t dynsm[];

    const int tid = threadIdx.x;
    const int lane = tid & 31;
    const int warp = tid >> 5;
    const int wm = warp & 1;
    const int wn = warp >> 1;
    const int gp = lane >> 2;
    const int tq = lane & 3;

    const int rowBase = blockIdx.y * 128;
    const int colBase = blockIdx.x * 128;
    const int warpRow = wm * 64;
    const int warpCol = wn * 64;

    uint32_t smem_u32 = (uint32_t)__cvta_generic_to_shared((void*)dynsm);

    float acc[4][8][4];
#pragma unroll
    for (int mi = 0; mi < 4; mi++)
#pragma unroll
        for (int ni = 0; ni < 8; ni++)
#pragma unroll
            for (int j = 0; j < 4; j++) acc[mi][ni][j] = 0.f;

    const int NT = DF / 32;

    auto load_stage = [&](int st, int k0) {
        uint32_t aBase = smem_u32 + (uint32_t)(st * G1_STAGE) * 4u;
        uint32_t bBase = aBase + (uint32_t)G1_AELEMS * 4u;
#pragma unroll
        for (int i = 0; i < 8; i++) {
            int fid = tid + i * 128;
            int r = fid >> 3, q = fid & 7;
            int gr = rowBase + r;
            bool ok = gr < NN;
            const float* src = A + (size_t)(ok ? gr : 0) * DF + k0 + q * 4;
            cp16(aBase + (uint32_t)(r * G1_ASTRIDE + q * 4) * 4u, src, ok);
        }
#pragma unroll
        for (int i = 0; i < 8; i++) {
            int fid = tid + i * 128;
            int r = fid >> 5, q = fid & 31;
            const float* src = B + (size_t)(k0 + r) * NH + colBase + q * 4;
            cp16(bBase + (uint32_t)(r * G1_BSTRIDE + q * 4) * 4u, src, true);
        }
    };

    load_stage(0, 0);
    asm volatile("cp.async.commit_group;\n");

    for (int t = 0; t < NT; t++) {
        if (t + 1 < NT) load_stage((t + 1) & 1, (t + 1) * 32);
        asm volatile("cp.async.commit_group;\n");
        if (t + 1 < NT) asm volatile("cp.async.wait_group 1;\n");
        else            asm volatile("cp.async.wait_group 0;\n");
        __syncthreads();

        const uint32_t* AsS = dynsm + (t & 1) * G1_STAGE;
        const uint32_t* BsS = AsS + G1_AELEMS;

#pragma unroll
        for (int kk = 0; kk < 32; kk += 8) {
            uint32_t a[4][4];
#pragma unroll
            for (int mi = 0; mi < 4; mi++) {
                int r0 = warpRow + mi * 16 + gp;
                a[mi][0] = f2tf32(__uint_as_float(AsS[r0 * G1_ASTRIDE + kk + tq]));
                a[mi][1] = f2tf32(__uint_as_float(AsS[(r0 + 8) * G1_ASTRIDE + kk + tq]));
                a[mi][2] = f2tf32(__uint_as_float(AsS[r0 * G1_ASTRIDE + kk + tq + 4]));
                a[mi][3] = f2tf32(__uint_as_float(AsS[(r0 + 8) * G1_ASTRIDE + kk + tq + 4]));
            }
            uint32_t b[8][2];
#pragma unroll
            for (int ni = 0; ni < 8; ni++) {
                int c = warpCol + ni * 8 + gp;
                b[ni][0] = f2tf32(__uint_as_float(BsS[(kk + tq) * G1_BSTRIDE + c]));
                b[ni][1] = f2tf32(__uint_as_float(BsS[(kk + tq + 4) * G1_BSTRIDE + c]));
            }
#pragma unroll
            for (int mi = 0; mi < 4; mi++)
#pragma unroll
                for (int ni = 0; ni < 8; ni++)
                    mma_tf32(acc[mi][ni][0], acc[mi][ni][1],
                             acc[mi][ni][2], acc[mi][ni][3],
                             a[mi][0], a[mi][1], a[mi][2], a[mi][3],
                             b[ni][0], b[ni][1]);
        }
        __syncthreads();
    }

    // ---- epilogue: store RAW accumulators (no dinv — removes prep dependency)
#pragma unroll
    for (int mi = 0; mi < 4; mi++) {
        int r0 = rowBase + warpRow + mi * 16 + gp;
        int r1 = r0 + 8;
#pragma unroll
        for (int ni = 0; ni < 8; ni++) {
            int c = colBase + warpCol + ni * 8 + tq * 2;
            if (r0 < NN) {
                float2 o = make_float2(acc[mi][ni][0], acc[mi][ni][1]);
                *(float2*)(g_h1 + (size_t)r0 * NH + c) = o;
            }
            if (r1 < NN) {
                float2 o = make_float2(acc[mi][ni][2], acc[mi][ni][3]);
                *(float2*)(g_h1 + (size_t)r1 * NH + c) = o;
            }
        }
    }
}

// ---------------- agg1: a1[i,f] = relu(dinv[i]*sum_{adj} dinv[r]*h1[r,f] + b1[f]) --------
__global__ __launch_bounds__(128) void k_agg1(const float* __restrict__ b1) {
    const int node = blockIdx.x;
    const int f = threadIdx.x * 4;
    const int s = g_offs[node], e = g_offs[node + 1];
    float4 acc = make_float4(0.f, 0.f, 0.f, 0.f);
    for (int p = s; p < e; p++) {
        int r = g_adj[p];
        float dr = __ldg(&g_dinv[r]);
        float4 v = *(const float4*)(g_h1 + (size_t)r * NH + f);
        acc.x += dr * v.x; acc.y += dr * v.y;
        acc.z += dr * v.z; acc.w += dr * v.w;
    }
    float d = g_dinv[node];
    float4 bb = *(const float4*)(b1 + f);
    float4 o;
    o.x = fmaxf(d * acc.x + bb.x, 0.f);
    o.y = fmaxf(d * acc.y + bb.y, 0.f);
    o.z = fmaxf(d * acc.z + bb.z, 0.f);
    o.w = fmaxf(d * acc.w + bb.w, 0.f);
    *(float4*)(g_a1 + (size_t)node * NH + f) = o;
}

// ---------------- GEMM2 (TF32, 2-stage cp.async A pipeline) ----------------
// g_h2[m,c] = dinv[m] * sum_k a1[m,k] * W2[k,c]
__global__ __launch_bounds__(256) void k_gemm2_tf32(const float* __restrict__ B) {
    __shared__ __align__(16) uint32_t Asr[2][128][36];
    __shared__ __align__(16) uint32_t Bs[32][72];

    const int tid = threadIdx.x;
    const int lane = tid & 31;
    const int warp = tid >> 5;
    const int wm = warp & 3;
    const int wn = warp >> 2;
    const int gp = lane >> 2;
    const int tq = lane & 3;

    const int rowBase = blockIdx.x * 128;
    const int warpRow = wm * 32;
    const int warpCol = wn * 32;

    uint32_t aSm = (uint32_t)__cvta_generic_to_shared((void*)&Asr[0][0][0]);

    float acc[2][4][4];
#pragma unroll
    for (int mi = 0; mi < 2; mi++)
#pragma unroll
        for (int ni = 0; ni < 4; ni++)
#pragma unroll
            for (int j = 0; j < 4; j++) acc[mi][ni][j] = 0.f;

    const int NT = NH / 32;

    auto load_stage = [&](int st, int k0) {
        uint32_t aBase = aSm + (uint32_t)(st * 128 * 36) * 4u;
#pragma unroll
        for (int i = 0; i < 4; i++) {
            int fid = tid + i * 256;
            int r = fid >> 3, q = fid & 7;
            int gr = rowBase + r;
            bool ok = gr < NN;
            const float* src = g_a1 + (size_t)(ok ? gr : 0) * NH + k0 + q * 4;
            cp16(aBase + (uint32_t)(r * 36 + q * 4) * 4u, src, ok);
        }
    };

    load_stage(0, 0);
    asm volatile("cp.async.commit_group;\n");

    for (int t = 0; t < NT; t++) {
        if (t + 1 < NT) load_stage((t + 1) & 1, (t + 1) * 32);
        asm volatile("cp.async.commit_group;\n");

#pragma unroll
        for (int i = 0; i < 8; i++) {
            int fid = tid + i * 256;
            int r = fid >> 6, c = fid & 63;
            float v = (c < NC) ? __ldg(B + (size_t)(t * 32 + r) * NC + c) : 0.f;
            if (c < 72) Bs[r][c] = f2tf32(v);
        }

        if (t + 1 < NT) asm volatile("cp.async.wait_group 1;\n");
        else            asm volatile("cp.async.wait_group 0;\n");
        __syncthreads();

        const uint32_t (*AsS)[36] = Asr[t & 1];

#pragma unroll
        for (int kk = 0; kk < 32; kk += 8) {
            uint32_t a[2][4];
#pragma unroll
            for (int mi = 0; mi < 2; mi++) {
                int r0 = warpRow + mi * 16 + gp;
                a[mi][0] = f2tf32(__uint_as_float(AsS[r0][kk + tq]));
                a[mi][1] = f2tf32(__uint_as_float(AsS[r0 + 8][kk + tq]));
                a[mi][2] = f2tf32(__uint_as_float(AsS[r0][kk + tq + 4]));
                a[mi][3] = f2tf32(__uint_as_float(AsS[r0 + 8][kk + tq + 4]));
            }
            uint32_t b[4][2];
#pragma unroll
            for (int ni = 0; ni < 4; ni++) {
                int c = warpCol + ni * 8 + gp;
                b[ni][0] = Bs[kk + tq][c];
                b[ni][1] = Bs[kk + tq + 4][c];
            }
#pragma unroll
            for (int mi = 0; mi < 2; mi++)
#pragma unroll
                for (int ni = 0; ni < 4; ni++)
                    mma_tf32(acc[mi][ni][0], acc[mi][ni][1],
                             acc[mi][ni][2], acc[mi][ni][3],
                             a[mi][0], a[mi][1], a[mi][2], a[mi][3],
                             b[ni][0], b[ni][1]);
        }
        __syncthreads();
    }

#pragma unroll
    for (int mi = 0; mi < 2; mi++) {
        int r0 = rowBase + warpRow + mi * 16 + gp;
        int r1 = r0 + 8;
        float d0 = (r0 < NN) ? g_dinv[r0] : 0.f;
        float d1 = (r1 < NN) ? g_dinv[r1] : 0.f;
#pragma unroll
        for (int ni = 0; ni < 4; ni++) {
            int c = warpCol + ni * 8 + tq * 2;
            if (r0 < NN) {
                if (c < NC)     g_h2[(size_t)r0 * NC + c]     = d0 * acc[mi][ni][0];
                if (c + 1 < NC) g_h2[(size_t)r0 * NC + c + 1] = d0 * acc[mi][ni][1];
            }
            if (r1 < NN) {
                if (c < NC)     g_h2[(size_t)r1 * NC + c]     = d1 * acc[mi][ni][2];
                if (c + 1 < NC) g_h2[(size_t)r1 * NC + c + 1] = d1 * acc[mi][ni][3];
            }
        }
    }
}

// ---------------- agg2: out[i,c] = dinv[i]*sum_{adj} h2[row,c] + b2[c] ----------------
__global__ __launch_bounds__(256) void k_agg2(const float* __restrict__ b2,
                                              float* __restrict__ out) {
    int node = blockIdx.x * 8 + (threadIdx.x >> 5);
    if (node >= NN) return;
    int lane = threadIdx.x & 31;
    int s = g_offs[node], e = g_offs[node + 1];
    float a0 = 0.f, a1 = 0.f;
    for (int p = s; p < e; p++) {
        int r = g_adj[p];
        const float* gp = g_h2 + (size_t)r * NC;
        a0 += gp[lane];
        if (lane + 32 < NC) a1 += gp[lane + 32];
    }
    float d = g_dinv[node];
    out[(size_t)node * NC + lane] = d * a0 + b2[lane];
    if (lane + 32 < NC)
        out[(size_t)node * NC + lane + 32] = d * a1 + b2[lane + 32];
}

// ---------------- launch ----------------
extern "C" void kernel_launch(void* const* d_in, const int* in_sizes, int n_in,
                              void* d_out, int out_size) {
    const float* x  = (const float*)d_in[0];
    const int*   ei = (const int*)d_in[1];   // [2, NE] int32
    const float* W1 = (const float*)d_in[2];
    const float* b1 = (const float*)d_in[3];
    const float* W2 = (const float*)d_in[4];
    const float* b2 = (const float*)d_in[5];
    float* out = (float*)d_out;

    const int* erow = ei;
    const int* ecol = ei + NE;

    // one-time host objects (created on the correctness call, before capture)
    static cudaStream_t s2 = nullptr;
    static cudaEvent_t evFork = nullptr, evJoin = nullptr;
    if (!s2) {
        cudaStreamCreateWithFlags(&s2, cudaStreamNonBlocking);
        cudaEventCreateWithFlags(&evFork, cudaEventDisableTiming);
        cudaEventCreateWithFlags(&evJoin, cudaEventDisableTiming);
        cudaFuncSetAttribute(k_gemm1_tf32,
                             cudaFuncAttributeMaxDynamicSharedMemorySize, G1_SMEM_BYTES);
    }

    // ---- fork: graph prep on side stream (independent of GEMM1)
    cudaEventRecord(evFork, 0);
    cudaStreamWaitEvent(s2, evFork, 0);
    k_init_deg<<<(NN + 255) / 256, 256, 0, s2>>>();
    k_count_deg<<<(NE + 255) / 256, 256, 0, s2>>>(ecol);
    k_scan_block<<<NSB, 512, 0, s2>>>();
    k_scan_finish2<<<(NN + 255) / 256, 256, 0, s2>>>();
    k_scatter<<<(NADJ + 255) / 256, 256, 0, s2>>>(erow, ecol);
    cudaEventRecord(evJoin, s2);

    // ---- main stream: layer 1 GEMM runs concurrently with prep
    dim3 g1(NH / 128, (NN + 127) / 128);
    k_gemm1_tf32<<<g1, 128, G1_SMEM_BYTES>>>(x, W1);

    // ---- join: everything below needs prep outputs
    cudaStreamWaitEvent(0, evJoin, 0);

    k_agg1<<<NN, 128>>>(b1);
    k_gemm2_tf32<<<(NN + 127) / 128, 256>>>(W2);
    k_agg2<<<(NN + 7) / 8, 256>>>(b2, out);
}

// round 12
// speedup vs baseline: 1.2425x; 1.0667x over previous
#include <cuda_runtime.h>
#include <cuda_fp16.h>
#include <cuda_bf16.h>
#include <cstdint>

// Problem constants
#define NN 50000
#define NE 150000
#define DF 512
#define NH 512
#define NC 47
#define NADJ (NE + NN)
#define NSB 98   // (NN+511)/512

// ---------------- scratch (static __device__ — no allocation) ----------------
__device__ int   g_deg[NN];
__device__ __align__(16) float g_dinv[NN];
__device__ int   g_incl[NN];
__device__ int   g_bsum[128];
__device__ int   g_offs[NN + 1];
__device__ int   g_cursor[NN];
__device__ int   g_adj[NADJ];
__device__ __align__(16) __half g_h1h[(size_t)NN * NH]; // RAW x@W1 (fp16, no dinv)
__device__ __align__(16) float g_a1[(size_t)NN * NH];   // relu(agg1 + b1)
__device__ __align__(16) float g_h2[(size_t)NN * NC];   // dinv-scaled layer2 pre-agg

// ---------------- graph prep ----------------
__global__ void k_init_deg() {
    int i = blockIdx.x * blockDim.x + threadIdx.x;
    if (i < NN) g_deg[i] = 1;  // self loop
}

__global__ void k_count_deg(const int* __restrict__ ecol) {
    int e = blockIdx.x * blockDim.x + threadIdx.x;
    if (e < NE) atomicAdd(&g_deg[ecol[e]], 1);
}

__global__ void k_scan_block() {
    __shared__ int s[512];
    int i = blockIdx.x * 512 + threadIdx.x;
    int v = (i < NN) ? g_deg[i] : 0;
    s[threadIdx.x] = v;
    __syncthreads();
    for (int off = 1; off < 512; off <<= 1) {
        int t = (threadIdx.x >= off) ? s[threadIdx.x - off] : 0;
        __syncthreads();
        s[threadIdx.x] += t;
        __syncthreads();
    }
    if (i < NN) g_incl[i] = s[threadIdx.x];
    if (threadIdx.x == 511) g_bsum[blockIdx.x] = s[511];  // raw block total
}

// finish: inline (redundant per-block) exclusive scan of the 98 block sums
__global__ void k_scan_finish2() {
    __shared__ int sx[128];
    int t = threadIdx.x;
    int v = 0;
    if (t < 128) { v = (t < NSB) ? g_bsum[t] : 0; sx[t] = v; }
    __syncthreads();
    for (int off = 1; off < 128; off <<= 1) {
        int u = 0;
        if (t < 128 && t >= off) u = sx[t - off];
        __syncthreads();
        if (t < 128) sx[t] += u;
        __syncthreads();
    }
    if (t < 128) sx[t] -= v;   // exclusive
    __syncthreads();
    int i = blockIdx.x * blockDim.x + t;
    if (i < NN) {
        int e = g_incl[i] - g_deg[i] + sx[i >> 9];
        g_offs[i] = e;
        g_cursor[i] = e;
        g_dinv[i] = rsqrtf((float)g_deg[i]);
    }
    if (i == 0) g_offs[NN] = NADJ;
}

__global__ void k_scatter(const int* __restrict__ erow,
                          const int* __restrict__ ecol) {
    int t = blockIdx.x * blockDim.x + threadIdx.x;
    if (t < NE) {
        int c = ecol[t];
        int p = atomicAdd(&g_cursor[c], 1);
        g_adj[p] = erow[t];
    } else if (t < NADJ) {
        int i = t - NE;
        int p = atomicAdd(&g_cursor[i], 1);
        g_adj[p] = i;
    }
}

// ---------------- helpers ----------------
__device__ __forceinline__ uint32_t f2tf32(float f) {
    uint32_t u;
    asm("cvt.rna.tf32.f32 %0, %1;" : "=r"(u) : "f"(f));
    return u;
}

__device__ __forceinline__ void mma_tf32(float& c0, float& c1, float& c2, float& c3,
                                         uint32_t a0, uint32_t a1, uint32_t a2, uint32_t a3,
                                         uint32_t b0, uint32_t b1) {
    asm volatile(
        "mma.sync.aligned.m16n8k8.row.col.f32.tf32.tf32.f32 "
        "{%0,%1,%2,%3},{%4,%5,%6,%7},{%8,%9},{%0,%1,%2,%3};"
        : "+f"(c0), "+f"(c1), "+f"(c2), "+f"(c3)
        : "r"(a0), "r"(a1), "r"(a2), "r"(a3), "r"(b0), "r"(b1));
}

__device__ __forceinline__ void cp16(uint32_t dst_smem, const void* src, bool pred) {
    int sz = pred ? 16 : 0;
    asm volatile("cp.async.cg.shared.global [%0], [%1], 16, %2;\n"
                 :: "r"(dst_smem), "l"(src), "r"(sz));
}

// ---------------- GEMM1 (TF32, 2-stage cp.async pipeline) ----------------
// g_h1h[m,f] = (half) sum_k x[m,k] * W1[k,f]   (RAW — dinv applied in agg1)
// BM=128, BN=128, BK=32; 128 threads = 4 warps (2M x 2N); warp tile 64x64.
#define G1_ASTRIDE 36
#define G1_BSTRIDE 136
#define G1_AELEMS (128 * G1_ASTRIDE)
#define G1_STAGE  (G1_AELEMS + 32 * G1_BSTRIDE)
#define G1_SMEM_BYTES (2 * G1_STAGE * 4)

__global__ __launch_bounds__(128) void k_gemm1_tf32(const float* __restrict__ A,
                                                    const float* __restrict__ B) {
    extern __shared__ __align__(16) uint32_t dynsm[];

    const int tid = threadIdx.x;
    const int lane = tid & 31;
    const int warp = tid >> 5;
    const int wm = warp & 1;
    const int wn = warp >> 1;
    const int gp = lane >> 2;
    const int tq = lane & 3;

    const int rowBase = blockIdx.y * 128;
    const int colBase = blockIdx.x * 128;
    const int warpRow = wm * 64;
    const int warpCol = wn * 64;

    uint32_t smem_u32 = (uint32_t)__cvta_generic_to_shared((void*)dynsm);

    float acc[4][8][4];
#pragma unroll
    for (int mi = 0; mi < 4; mi++)
#pragma unroll
        for (int ni = 0; ni < 8; ni++)
#pragma unroll
            for (int j = 0; j < 4; j++) acc[mi][ni][j] = 0.f;

    const int NT = DF / 32;

    auto load_stage = [&](int st, int k0) {
        uint32_t aBase = smem_u32 + (uint32_t)(st * G1_STAGE) * 4u;
        uint32_t bBase = aBase + (uint32_t)G1_AELEMS * 4u;
#pragma unroll
        for (int i = 0; i < 8; i++) {
            int fid = tid + i * 128;
            int r = fid >> 3, q = fid & 7;
            int gr = rowBase + r;
            bool ok = gr < NN;
            const float* src = A + (size_t)(ok ? gr : 0) * DF + k0 + q * 4;
            cp16(aBase + (uint32_t)(r * G1_ASTRIDE + q * 4) * 4u, src, ok);
        }
#pragma unroll
        for (int i = 0; i < 8; i++) {
            int fid = tid + i * 128;
            int r = fid >> 5, q = fid & 31;
            const float* src = B + (size_t)(k0 + r) * NH + colBase + q * 4;
            cp16(bBase + (uint32_t)(r * G1_BSTRIDE + q * 4) * 4u, src, true);
        }
    };

    load_stage(0, 0);
    asm volatile("cp.async.commit_group;\n");

    for (int t = 0; t < NT; t++) {
        if (t + 1 < NT) load_stage((t + 1) & 1, (t + 1) * 32);
        asm volatile("cp.async.commit_group;\n");
        if (t + 1 < NT) asm volatile("cp.async.wait_group 1;\n");
        else            asm volatile("cp.async.wait_group 0;\n");
        __syncthreads();

        const uint32_t* AsS = dynsm + (t & 1) * G1_STAGE;
        const uint32_t* BsS = AsS + G1_AELEMS;

#pragma unroll
        for (int kk = 0; kk < 32; kk += 8) {
            uint32_t a[4][4];
#pragma unroll
            for (int mi = 0; mi < 4; mi++) {
                int r0 = warpRow + mi * 16 + gp;
                a[mi][0] = f2tf32(__uint_as_float(AsS[r0 * G1_ASTRIDE + kk + tq]));
                a[mi][1] = f2tf32(__uint_as_float(AsS[(r0 + 8) * G1_ASTRIDE + kk + tq]));
                a[mi][2] = f2tf32(__uint_as_float(AsS[r0 * G1_ASTRIDE + kk + tq + 4]));
                a[mi][3] = f2tf32(__uint_as_float(AsS[(r0 + 8) * G1_ASTRIDE + kk + tq + 4]));
            }
            uint32_t b[8][2];
#pragma unroll
            for (int ni = 0; ni < 8; ni++) {
                int c = warpCol + ni * 8 + gp;
                b[ni][0] = f2tf32(__uint_as_float(BsS[(kk + tq) * G1_BSTRIDE + c]));
                b[ni][1] = f2tf32(__uint_as_float(BsS[(kk + tq + 4) * G1_BSTRIDE + c]));
            }
#pragma unroll
            for (int mi = 0; mi < 4; mi++)
#pragma unroll
                for (int ni = 0; ni < 8; ni++)
                    mma_tf32(acc[mi][ni][0], acc[mi][ni][1],
                             acc[mi][ni][2], acc[mi][ni][3],
                             a[mi][0], a[mi][1], a[mi][2], a[mi][3],
                             b[ni][0], b[ni][1]);
        }
        __syncthreads();
    }

    // ---- epilogue: store RAW accumulators as fp16 (no dinv)
#pragma unroll
    for (int mi = 0; mi < 4; mi++) {
        int r0 = rowBase + warpRow + mi * 16 + gp;
        int r1 = r0 + 8;
#pragma unroll
        for (int ni = 0; ni < 8; ni++) {
            int c = colBase + warpCol + ni * 8 + tq * 2;
            if (r0 < NN) {
                __half2 o = __float22half2_rn(make_float2(acc[mi][ni][0], acc[mi][ni][1]));
                *(__half2*)(g_h1h + (size_t)r0 * NH + c) = o;
            }
            if (r1 < NN) {
                __half2 o = __float22half2_rn(make_float2(acc[mi][ni][2], acc[mi][ni][3]));
                *(__half2*)(g_h1h + (size_t)r1 * NH + c) = o;
            }
        }
    }
}

// ---------------- agg1: a1[i,f] = relu(dinv[i]*sum_{adj} dinv[r]*h1[r,f] + b1[f]) --------
__global__ __launch_bounds__(128) void k_agg1(const float* __restrict__ b1) {
    const int node = blockIdx.x;
    const int f = threadIdx.x * 4;
    const int s = g_offs[node], e = g_offs[node + 1];
    float4 acc = make_float4(0.f, 0.f, 0.f, 0.f);
    for (int p = s; p < e; p++) {
        int r = g_adj[p];
        float dr = __ldg(&g_dinv[r]);
        // 4 halves = 8 bytes
        uint2 raw = *(const uint2*)(g_h1h + (size_t)r * NH + f);
        __half2 h01 = *(__half2*)&raw.x;
        __half2 h23 = *(__half2*)&raw.y;
        float2 v01 = __half22float2(h01);
        float2 v23 = __half22float2(h23);
        acc.x += dr * v01.x; acc.y += dr * v01.y;
        acc.z += dr * v23.x; acc.w += dr * v23.y;
    }
    float d = g_dinv[node];
    float4 bb = *(const float4*)(b1 + f);
    float4 o;
    o.x = fmaxf(d * acc.x + bb.x, 0.f);
    o.y = fmaxf(d * acc.y + bb.y, 0.f);
    o.z = fmaxf(d * acc.z + bb.z, 0.f);
    o.w = fmaxf(d * acc.w + bb.w, 0.f);
    *(float4*)(g_a1 + (size_t)node * NH + f) = o;
}

// ---------------- GEMM2 (TF32, 2-stage cp.async A pipeline) ----------------
// g_h2[m,c] = dinv[m] * sum_k a1[m,k] * W2[k,c]
__global__ __launch_bounds__(256) void k_gemm2_tf32(const float* __restrict__ B) {
    __shared__ __align__(16) uint32_t Asr[2][128][36];
    __shared__ __align__(16) uint32_t Bs[32][72];

    const int tid = threadIdx.x;
    const int lane = tid & 31;
    const int warp = tid >> 5;
    const int wm = warp & 3;
    const int wn = warp >> 2;
    const int gp = lane >> 2;
    const int tq = lane & 3;

    const int rowBase = blockIdx.x * 128;
    const int warpRow = wm * 32;
    const int warpCol = wn * 32;

    uint32_t aSm = (uint32_t)__cvta_generic_to_shared((void*)&Asr[0][0][0]);

    float acc[2][4][4];
#pragma unroll
    for (int mi = 0; mi < 2; mi++)
#pragma unroll
        for (int ni = 0; ni < 4; ni++)
#pragma unroll
            for (int j = 0; j < 4; j++) acc[mi][ni][j] = 0.f;

    const int NT = NH / 32;

    auto load_stage = [&](int st, int k0) {
        uint32_t aBase = aSm + (uint32_t)(st * 128 * 36) * 4u;
#pragma unroll
        for (int i = 0; i < 4; i++) {
            int fid = tid + i * 256;
            int r = fid >> 3, q = fid & 7;
            int gr = rowBase + r;
            bool ok = gr < NN;
            const float* src = g_a1 + (size_t)(ok ? gr : 0) * NH + k0 + q * 4;
            cp16(aBase + (uint32_t)(r * 36 + q * 4) * 4u, src, ok);
        }
    };

    load_stage(0, 0);
    asm volatile("cp.async.commit_group;\n");

    for (int t = 0; t < NT; t++) {
        if (t + 1 < NT) load_stage((t + 1) & 1, (t + 1) * 32);
        asm volatile("cp.async.commit_group;\n");

#pragma unroll
        for (int i = 0; i < 8; i++) {
            int fid = tid + i * 256;
            int r = fid >> 6, c = fid & 63;
            float v = (c < NC) ? __ldg(B + (size_t)(t * 32 + r) * NC + c) : 0.f;
            if (c < 72) Bs[r][c] = f2tf32(v);
        }

        if (t + 1 < NT) asm volatile("cp.async.wait_group 1;\n");
        else            asm volatile("cp.async.wait_group 0;\n");
        __syncthreads();

        const uint32_t (*AsS)[36] = Asr[t & 1];

#pragma unroll
        for (int kk = 0; kk < 32; kk += 8) {
            uint32_t a[2][4];
#pragma unroll
            for (int mi = 0; mi < 2; mi++) {
                int r0 = warpRow + mi * 16 + gp;
                a[mi][0] = f2tf32(__uint_as_float(AsS[r0][kk + tq]));
                a[mi][1] = f2tf32(__uint_as_float(AsS[r0 + 8][kk + tq]));
                a[mi][2] = f2tf32(__uint_as_float(AsS[r0][kk + tq + 4]));
                a[mi][3] = f2tf32(__uint_as_float(AsS[r0 + 8][kk + tq + 4]));
            }
            uint32_t b[4][2];
#pragma unroll
            for (int ni = 0; ni < 4; ni++) {
                int c = warpCol + ni * 8 + gp;
                b[ni][0] = Bs[kk + tq][c];
                b[ni][1] = Bs[kk + tq + 4][c];
            }
#pragma unroll
            for (int mi = 0; mi < 2; mi++)
#pragma unroll
                for (int ni = 0; ni < 4; ni++)
                    mma_tf32(acc[mi][ni][0], acc[mi][ni][1],
                             acc[mi][ni][2], acc[mi][ni][3],
                             a[mi][0], a[mi][1], a[mi][2], a[mi][3],
                             b[ni][0], b[ni][1]);
        }
        __syncthreads();
    }

#pragma unroll
    for (int mi = 0; mi < 2; mi++) {
        int r0 = rowBase + warpRow + mi * 16 + gp;
        int r1 = r0 + 8;
        float d0 = (r0 < NN) ? g_dinv[r0] : 0.f;
        float d1 = (r1 < NN) ? g_dinv[r1] : 0.f;
#pragma unroll
        for (int ni = 0; ni < 4; ni++) {
            int c = warpCol + ni * 8 + tq * 2;
            if (r0 < NN) {
                if (c < NC)     g_h2[(size_t)r0 * NC + c]     = d0 * acc[mi][ni][0];
                if (c + 1 < NC) g_h2[(size_t)r0 * NC + c + 1] = d0 * acc[mi][ni][1];
            }
            if (r1 < NN) {
                if (c < NC)     g_h2[(size_t)r1 * NC + c]     = d1 * acc[mi][ni][2];
                if (c + 1 < NC) g_h2[(size_t)r1 * NC + c + 1] = d1 * acc[mi][ni][3];
            }
        }
    }
}

// ---------------- agg2: out[i,c] = dinv[i]*sum_{adj} h2[row,c] + b2[c] ----------------
__global__ __launch_bounds__(256) void k_agg2(const float* __restrict__ b2,
                                              float* __restrict__ out) {
    int node = blockIdx.x * 8 + (threadIdx.x >> 5);
    if (node >= NN) return;
    int lane = threadIdx.x & 31;
    int s = g_offs[node], e = g_offs[node + 1];
    float a0 = 0.f, a1 = 0.f;
    for (int p = s; p < e; p++) {
        int r = g_adj[p];
        const float* gp = g_h2 + (size_t)r * NC;
        a0 += gp[lane];
        if (lane + 32 < NC) a1 += gp[lane + 32];
    }
    float d = g_dinv[node];
    out[(size_t)node * NC + lane] = d * a0 + b2[lane];
    if (lane + 32 < NC)
        out[(size_t)node * NC + lane + 32] = d * a1 + b2[lane + 32];
}

// ---------------- launch ----------------
extern "C" void kernel_launch(void* const* d_in, const int* in_sizes, int n_in,
                              void* d_out, int out_size) {
    const float* x  = (const float*)d_in[0];
    const int*   ei = (const int*)d_in[1];   // [2, NE] int32
    const float* W1 = (const float*)d_in[2];
    const float* b1 = (const float*)d_in[3];
    const float* W2 = (const float*)d_in[4];
    const float* b2 = (const float*)d_in[5];
    float* out = (float*)d_out;

    const int* erow = ei;
    const int* ecol = ei + NE;

    // one-time host objects (created on the correctness call, before capture)
    static cudaStream_t s2 = nullptr;
    static cudaEvent_t evFork = nullptr, evJoin = nullptr;
    if (!s2) {
        cudaStreamCreateWithFlags(&s2, cudaStreamNonBlocking);
        cudaEventCreateWithFlags(&evFork, cudaEventDisableTiming);
        cudaEventCreateWithFlags(&evJoin, cudaEventDisableTiming);
        cudaFuncSetAttribute(k_gemm1_tf32,
                             cudaFuncAttributeMaxDynamicSharedMemorySize, G1_SMEM_BYTES);
    }

    // ---- fork: graph prep on side stream (independent of GEMM1)
    cudaEventRecord(evFork, 0);
    cudaStreamWaitEvent(s2, evFork, 0);
    k_init_deg<<<(NN + 255) / 256, 256, 0, s2>>>();
    k_count_deg<<<(NE + 255) / 256, 256, 0, s2>>>(ecol);
    k_scan_block<<<NSB, 512, 0, s2>>>();
    k_scan_finish2<<<(NN + 255) / 256, 256, 0, s2>>>();
    k_scatter<<<(NADJ + 255) / 256, 256, 0, s2>>>(erow, ecol);
    cudaEventRecord(evJoin, s2);

    // ---- main stream: layer 1 GEMM runs concurrently with prep
    dim3 g1(NH / 128, (NN + 127) / 128);
    k_gemm1_tf32<<<g1, 128, G1_SMEM_BYTES>>>(x, W1);

    // ---- join: everything below needs prep outputs
    cudaStreamWaitEvent(0, evJoin, 0);

    k_agg1<<<NN, 128>>>(b1);
    k_gemm2_tf32<<<(NN + 127) / 128, 256>>>(W2);
    k_agg2<<<(NN + 7) / 8, 256>>>(b2, out);
}

// round 13
// speedup vs baseline: 1.4785x; 1.1899x over previous
#include <cuda_runtime.h>
#include <cuda_fp16.h>
#include <cuda_bf16.h>
#include <cstdint>

// Problem constants
#define NN 50000
#define NE 150000
#define DF 512
#define NH 512
#define NC 47
#define NADJ (NE + NN)
#define NSB 98   // (NN+511)/512

// ---------------- scratch (static __device__ — no allocation) ----------------
__device__ int   g_deg[NN];
__device__ __align__(16) float g_dinv[NN];
__device__ int   g_incl[NN];
__device__ int   g_bsum[128];
__device__ int   g_offs[NN + 1];
__device__ int   g_cursor[NN];
__device__ int   g_adj[NADJ];
__device__ __align__(16) __half   g_xh[(size_t)NN * DF];      // fp16 copy of x
__device__ __align__(16) uint32_t g_W1p[(DF / 2) * NH];       // W1 packed: [kpair][n] = half2(W1[2k][n],W1[2k+1][n])
__device__ __align__(16) __half g_h1h[(size_t)NN * NH]; // RAW x@W1 (fp16, no dinv)
__device__ __align__(16) float g_a1[(size_t)NN * NH];   // relu(agg1 + b1)
__device__ __align__(16) float g_h2[(size_t)NN * NC];   // dinv-scaled layer2 pre-agg

// ---------------- graph prep ----------------
__global__ void k_init_deg() {
    int i = blockIdx.x * blockDim.x + threadIdx.x;
    if (i < NN) g_deg[i] = 1;  // self loop
}

__global__ void k_count_deg(const int* __restrict__ ecol) {
    int e = blockIdx.x * blockDim.x + threadIdx.x;
    if (e < NE) atomicAdd(&g_deg[ecol[e]], 1);
}

__global__ void k_scan_block() {
    __shared__ int s[512];
    int i = blockIdx.x * 512 + threadIdx.x;
    int v = (i < NN) ? g_deg[i] : 0;
    s[threadIdx.x] = v;
    __syncthreads();
    for (int off = 1; off < 512; off <<= 1) {
        int t = (threadIdx.x >= off) ? s[threadIdx.x - off] : 0;
        __syncthreads();
        s[threadIdx.x] += t;
        __syncthreads();
    }
    if (i < NN) g_incl[i] = s[threadIdx.x];
    if (threadIdx.x == 511) g_bsum[blockIdx.x] = s[511];
}

__global__ void k_scan_finish2() {
    __shared__ int sx[128];
    int t = threadIdx.x;
    int v = 0;
    if (t < 128) { v = (t < NSB) ? g_bsum[t] : 0; sx[t] = v; }
    __syncthreads();
    for (int off = 1; off < 128; off <<= 1) {
        int u = 0;
        if (t < 128 && t >= off) u = sx[t - off];
        __syncthreads();
        if (t < 128) sx[t] += u;
        __syncthreads();
    }
    if (t < 128) sx[t] -= v;   // exclusive
    __syncthreads();
    int i = blockIdx.x * blockDim.x + t;
    if (i < NN) {
        int e = g_incl[i] - g_deg[i] + sx[i >> 9];
        g_offs[i] = e;
        g_cursor[i] = e;
        g_dinv[i] = rsqrtf((float)g_deg[i]);
    }
    if (i == 0) g_offs[NN] = NADJ;
}

__global__ void k_scatter(const int* __restrict__ erow,
                          const int* __restrict__ ecol) {
    int t = blockIdx.x * blockDim.x + threadIdx.x;
    if (t < NE) {
        int c = ecol[t];
        int p = atomicAdd(&g_cursor[c], 1);
        g_adj[p] = erow[t];
    } else if (t < NADJ) {
        int i = t - NE;
        int p = atomicAdd(&g_cursor[i], 1);
        g_adj[p] = i;
    }
}

// ---------------- conversions ----------------
__global__ void k_xcvt(const float* __restrict__ x) {
    size_t i = (size_t)blockIdx.x * 256 + threadIdx.x;   // float4 index
    if (i < (size_t)NN * DF / 4) {
        float4 v = __ldg((const float4*)x + i);
        __half2 h0 = __float22half2_rn(make_float2(v.x, v.y));
        __half2 h1 = __float22half2_rn(make_float2(v.z, v.w));
        uint2 o;
        o.x = *(uint32_t*)&h0;
        o.y = *(uint32_t*)&h1;
        *((uint2*)g_xh + i) = o;
    }
}

__global__ void k_w1p(const float* __restrict__ W1) {
    int i = blockIdx.x * 256 + threadIdx.x;   // word index
    if (i < (DF / 2) * NH) {
        int kp = i >> 9;        // 0..255
        int n = i & (NH - 1);
        float lo = __ldg(W1 + (size_t)(2 * kp) * NH + n);
        float hi = __ldg(W1 + (size_t)(2 * kp + 1) * NH + n);
        __half2 h = __float22half2_rn(make_float2(lo, hi));
        g_W1p[i] = *(uint32_t*)&h;
    }
}

// ---------------- helpers ----------------
__device__ __forceinline__ uint32_t f2tf32(float f) {
    uint32_t u;
    asm("cvt.rna.tf32.f32 %0, %1;" : "=r"(u) : "f"(f));
    return u;
}

__device__ __forceinline__ void mma_tf32(float& c0, float& c1, float& c2, float& c3,
                                         uint32_t a0, uint32_t a1, uint32_t a2, uint32_t a3,
                                         uint32_t b0, uint32_t b1) {
    asm volatile(
        "mma.sync.aligned.m16n8k8.row.col.f32.tf32.tf32.f32 "
        "{%0,%1,%2,%3},{%4,%5,%6,%7},{%8,%9},{%0,%1,%2,%3};"
        : "+f"(c0), "+f"(c1), "+f"(c2), "+f"(c3)
        : "r"(a0), "r"(a1), "r"(a2), "r"(a3), "r"(b0), "r"(b1));
}

__device__ __forceinline__ void mma_f16(float& c0, float& c1, float& c2, float& c3,
                                        uint32_t a0, uint32_t a1, uint32_t a2, uint32_t a3,
                                        uint32_t b0, uint32_t b1) {
    asm volatile(
        "mma.sync.aligned.m16n8k16.row.col.f32.f16.f16.f32 "
        "{%0,%1,%2,%3},{%4,%5,%6,%7},{%8,%9},{%0,%1,%2,%3};"
        : "+f"(c0), "+f"(c1), "+f"(c2), "+f"(c3)
        : "r"(a0), "r"(a1), "r"(a2), "r"(a3), "r"(b0), "r"(b1));
}

__device__ __forceinline__ void cp16(uint32_t dst_smem, const void* src, bool pred) {
    int sz = pred ? 16 : 0;
    asm volatile("cp.async.cg.shared.global [%0], [%1], 16, %2;\n"
                 :: "r"(dst_smem), "l"(src), "r"(sz));
}

// ---------------- GEMM1 (FP16 HMMA, 2-stage cp.async pipeline) ----------------
// g_h1h[m,f] = (half) sum_k xh[m,k] * W1p[k,f]   (RAW — dinv applied in agg1)
// BM=128, BN=128, BK=32; 128 threads = 4 warps (2M x 2N); warp tile 64x64.
// A stage: [128 rows][16 kpair words] stride 20 (banks 20*gp+tq distinct)
// B stage: [16 kpair rows][128 n words] stride 136 (banks 8*tq+gp distinct)
#define H1_ASTRIDE 20
#define H1_AELEMS (128 * H1_ASTRIDE)                // 2560 words
#define H1_BSTRIDE 136
#define H1_STAGE  (H1_AELEMS + 16 * H1_BSTRIDE)     // 4736 words
#define H1_SMEM_BYTES (2 * H1_STAGE * 4)            // 37888 B

__global__ __launch_bounds__(128) void k_gemm1_f16() {
    extern __shared__ __align__(16) uint32_t dynsm[];

    const int tid = threadIdx.x;
    const int lane = tid & 31;
    const int warp = tid >> 5;
    const int wm = warp & 1;
    const int wn = warp >> 1;
    const int gp = lane >> 2;
    const int tq = lane & 3;

    const int rowBase = blockIdx.y * 128;
    const int colBase = blockIdx.x * 128;
    const int warpRow = wm * 64;
    const int warpCol = wn * 64;

    uint32_t smem_u32 = (uint32_t)__cvta_generic_to_shared((void*)dynsm);

    float acc[4][8][4];
#pragma unroll
    for (int mi = 0; mi < 4; mi++)
#pragma unroll
        for (int ni = 0; ni < 8; ni++)
#pragma unroll
            for (int j = 0; j < 4; j++) acc[mi][ni][j] = 0.f;

    const int NT = DF / 32;   // 16 k-tiles of 32

    auto load_stage = [&](int st, int t) {
        uint32_t aBase = smem_u32 + (uint32_t)(st * H1_STAGE) * 4u;
        uint32_t bBase = aBase + (uint32_t)H1_AELEMS * 4u;
        // A: 128 rows x 64 B (32 halves) = 512 chunks of 16B -> 4/thread
#pragma unroll
        for (int i = 0; i < 4; i++) {
            int fid = tid + i * 128;
            int r = fid >> 2, q = fid & 3;          // q: 16B chunk within row
            int gr = rowBase + r;
            bool ok = gr < NN;
            const __half* src = g_xh + (size_t)(ok ? gr : 0) * DF + t * 32 + q * 8;
            cp16(aBase + (uint32_t)(r * H1_ASTRIDE + q * 4) * 4u, src, ok);
        }
        // B: 16 kpair rows x 512 B (128 words) = 512 chunks -> 4/thread
#pragma unroll
        for (int i = 0; i < 4; i++) {
            int fid = tid + i * 128;
            int r = fid >> 5, q = fid & 31;         // q: 16B chunk (4 words)
            const uint32_t* src = g_W1p + (size_t)(t * 16 + r) * NH + colBase + q * 4;
            cp16(bBase + (uint32_t)(r * H1_BSTRIDE + q * 4) * 4u, src, true);
        }
    };

    load_stage(0, 0);
    asm volatile("cp.async.commit_group;\n");

    for (int t = 0; t < NT; t++) {
        if (t + 1 < NT) load_stage((t + 1) & 1, t + 1);
        asm volatile("cp.async.commit_group;\n");
        if (t + 1 < NT) asm volatile("cp.async.wait_group 1;\n");
        else            asm volatile("cp.async.wait_group 0;\n");
        __syncthreads();

        const uint32_t* AsS = dynsm + (t & 1) * H1_STAGE;
        const uint32_t* BsS = AsS + H1_AELEMS;

        // two k16 steps per 32-k tile: kpair base 0 and 8
#pragma unroll
        for (int kk2 = 0; kk2 < 16; kk2 += 8) {
            uint32_t a[4][4];
#pragma unroll
            for (int mi = 0; mi < 4; mi++) {
                int r0 = warpRow + mi * 16 + gp;
                a[mi][0] = AsS[r0 * H1_ASTRIDE + kk2 + tq];
                a[mi][1] = AsS[(r0 + 8) * H1_ASTRIDE + kk2 + tq];
                a[mi][2] = AsS[r0 * H1_ASTRIDE + kk2 + tq + 4];
                a[mi][3] = AsS[(r0 + 8) * H1_ASTRIDE + kk2 + tq + 4];
            }
            uint32_t b[8][2];
#pragma unroll
            for (int ni = 0; ni < 8; ni++) {
                int c = warpCol + ni * 8 + gp;
                b[ni][0] = BsS[(kk2 + tq) * H1_BSTRIDE + c];
                b[ni][1] = BsS[(kk2 + tq + 4) * H1_BSTRIDE + c];
            }
#pragma unroll
            for (int mi = 0; mi < 4; mi++)
#pragma unroll
                for (int ni = 0; ni < 8; ni++)
                    mma_f16(acc[mi][ni][0], acc[mi][ni][1],
                            acc[mi][ni][2], acc[mi][ni][3],
                            a[mi][0], a[mi][1], a[mi][2], a[mi][3],
                            b[ni][0], b[ni][1]);
        }
        __syncthreads();
    }

    // ---- epilogue: store RAW accumulators as fp16 (no dinv)
#pragma unroll
    for (int mi = 0; mi < 4; mi++) {
        int r0 = rowBase + warpRow + mi * 16 + gp;
        int r1 = r0 + 8;
#pragma unroll
        for (int ni = 0; ni < 8; ni++) {
            int c = colBase + warpCol + ni * 8 + tq * 2;
            if (r0 < NN) {
                __half2 o = __float22half2_rn(make_float2(acc[mi][ni][0], acc[mi][ni][1]));
                *(__half2*)(g_h1h + (size_t)r0 * NH + c) = o;
            }
            if (r1 < NN) {
                __half2 o = __float22half2_rn(make_float2(acc[mi][ni][2], acc[mi][ni][3]));
                *(__half2*)(g_h1h + (size_t)r1 * NH + c) = o;
            }
        }
    }
}

// ---------------- agg1: a1[i,f] = relu(dinv[i]*sum_{adj} dinv[r]*h1[r,f] + b1[f]) --------
__global__ __launch_bounds__(128) void k_agg1(const float* __restrict__ b1) {
    const int node = blockIdx.x;
    const int f = threadIdx.x * 4;
    const int s = g_offs[node], e = g_offs[node + 1];
    float4 acc = make_float4(0.f, 0.f, 0.f, 0.f);
    for (int p = s; p < e; p++) {
        int r = g_adj[p];
        float dr = __ldg(&g_dinv[r]);
        uint2 raw = *(const uint2*)(g_h1h + (size_t)r * NH + f);
        __half2 h01 = *(__half2*)&raw.x;
        __half2 h23 = *(__half2*)&raw.y;
        float2 v01 = __half22float2(h01);
        float2 v23 = __half22float2(h23);
        acc.x += dr * v01.x; acc.y += dr * v01.y;
        acc.z += dr * v23.x; acc.w += dr * v23.y;
    }
    float d = g_dinv[node];
    float4 bb = *(const float4*)(b1 + f);
    float4 o;
    o.x = fmaxf(d * acc.x + bb.x, 0.f);
    o.y = fmaxf(d * acc.y + bb.y, 0.f);
    o.z = fmaxf(d * acc.z + bb.z, 0.f);
    o.w = fmaxf(d * acc.w + bb.w, 0.f);
    *(float4*)(g_a1 + (size_t)node * NH + f) = o;
}

// ---------------- GEMM2 (TF32, 2-stage cp.async A pipeline) ----------------
// g_h2[m,c] = dinv[m] * sum_k a1[m,k] * W2[k,c]
__global__ __launch_bounds__(256) void k_gemm2_tf32(const float* __restrict__ B) {
    __shared__ __align__(16) uint32_t Asr[2][128][36];
    __shared__ __align__(16) uint32_t Bs[32][72];

    const int tid = threadIdx.x;
    const int lane = tid & 31;
    const int warp = tid >> 5;
    const int wm = warp & 3;
    const int wn = warp >> 2;
    const int gp = lane >> 2;
    const int tq = lane & 3;

    const int rowBase = blockIdx.x * 128;
    const int warpRow = wm * 32;
    const int warpCol = wn * 32;

    uint32_t aSm = (uint32_t)__cvta_generic_to_shared((void*)&Asr[0][0][0]);

    float acc[2][4][4];
#pragma unroll
    for (int mi = 0; mi < 2; mi++)
#pragma unroll
        for (int ni = 0; ni < 4; ni++)
#pragma unroll
            for (int j = 0; j < 4; j++) acc[mi][ni][j] = 0.f;

    const int NT = NH / 32;

    auto load_stage = [&](int st, int k0) {
        uint32_t aBase = aSm + (uint32_t)(st * 128 * 36) * 4u;
#pragma unroll
        for (int i = 0; i < 4; i++) {
            int fid = tid + i * 256;
            int r = fid >> 3, q = fid & 7;
            int gr = rowBase + r;
            bool ok = gr < NN;
            const float* src = g_a1 + (size_t)(ok ? gr : 0) * NH + k0 + q * 4;
            cp16(aBase + (uint32_t)(r * 36 + q * 4) * 4u, src, ok);
        }
    };

    load_stage(0, 0);
    asm volatile("cp.async.commit_group;\n");

    for (int t = 0; t < NT; t++) {
        if (t + 1 < NT) load_stage((t + 1) & 1, (t + 1) * 32);
        asm volatile("cp.async.commit_group;\n");

#pragma unroll
        for (int i = 0; i < 8; i++) {
            int fid = tid + i * 256;
            int r = fid >> 6, c = fid & 63;
            float v = (c < NC) ? __ldg(B + (size_t)(t * 32 + r) * NC + c) : 0.f;
            if (c < 72) Bs[r][c] = f2tf32(v);
        }

        if (t + 1 < NT) asm volatile("cp.async.wait_group 1;\n");
        else            asm volatile("cp.async.wait_group 0;\n");
        __syncthreads();

        const uint32_t (*AsS)[36] = Asr[t & 1];

#pragma unroll
        for (int kk = 0; kk < 32; kk += 8) {
            uint32_t a[2][4];
#pragma unroll
            for (int mi = 0; mi < 2; mi++) {
                int r0 = warpRow + mi * 16 + gp;
                a[mi][0] = f2tf32(__uint_as_float(AsS[r0][kk + tq]));
                a[mi][1] = f2tf32(__uint_as_float(AsS[r0 + 8][kk + tq]));
                a[mi][2] = f2tf32(__uint_as_float(AsS[r0][kk + tq + 4]));
                a[mi][3] = f2tf32(__uint_as_float(AsS[r0 + 8][kk + tq + 4]));
            }
            uint32_t b[4][2];
#pragma unroll
            for (int ni = 0; ni < 4; ni++) {
                int c = warpCol + ni * 8 + gp;
                b[ni][0] = Bs[kk + tq][c];
                b[ni][1] = Bs[kk + tq + 4][c];
            }
#pragma unroll
            for (int mi = 0; mi < 2; mi++)
#pragma unroll
                for (int ni = 0; ni < 4; ni++)
                    mma_tf32(acc[mi][ni][0], acc[mi][ni][1],
                             acc[mi][ni][2], acc[mi][ni][3],
                             a[mi][0], a[mi][1], a[mi][2], a[mi][3],
                             b[ni][0], b[ni][1]);
        }
        __syncthreads();
    }

#pragma unroll
    for (int mi = 0; mi < 2; mi++) {
        int r0 = rowBase + warpRow + mi * 16 + gp;
        int r1 = r0 + 8;
        float d0 = (r0 < NN) ? g_dinv[r0] : 0.f;
        float d1 = (r1 < NN) ? g_dinv[r1] : 0.f;
#pragma unroll
        for (int ni = 0; ni < 4; ni++) {
            int c = warpCol + ni * 8 + tq * 2;
            if (r0 < NN) {
                if (c < NC)     g_h2[(size_t)r0 * NC + c]     = d0 * acc[mi][ni][0];
                if (c + 1 < NC) g_h2[(size_t)r0 * NC + c + 1] = d0 * acc[mi][ni][1];
            }
            if (r1 < NN) {
                if (c < NC)     g_h2[(size_t)r1 * NC + c]     = d1 * acc[mi][ni][2];
                if (c + 1 < NC) g_h2[(size_t)r1 * NC + c + 1] = d1 * acc[mi][ni][3];
            }
        }
    }
}

// ---------------- agg2: out[i,c] = dinv[i]*sum_{adj} h2[row,c] + b2[c] ----------------
__global__ __launch_bounds__(256) void k_agg2(const float* __restrict__ b2,
                                              float* __restrict__ out) {
    int node = blockIdx.x * 8 + (threadIdx.x >> 5);
    if (node >= NN) return;
    int lane = threadIdx.x & 31;
    int s = g_offs[node], e = g_offs[node + 1];
    float a0 = 0.f, a1 = 0.f;
    for (int p = s; p < e; p++) {
        int r = g_adj[p];
        const float* gp = g_h2 + (size_t)r * NC;
        a0 += gp[lane];
        if (lane + 32 < NC) a1 += gp[lane + 32];
    }
    float d = g_dinv[node];
    out[(size_t)node * NC + lane] = d * a0 + b2[lane];
    if (lane + 32 < NC)
        out[(size_t)node * NC + lane + 32] = d * a1 + b2[lane + 32];
}

// ---------------- launch ----------------
extern "C" void kernel_launch(void* const* d_in, const int* in_sizes, int n_in,
                              void* d_out, int out_size) {
    const float* x  = (const float*)d_in[0];
    const int*   ei = (const int*)d_in[1];   // [2, NE] int32
    const float* W1 = (const float*)d_in[2];
    const float* b1 = (const float*)d_in[3];
    const float* W2 = (const float*)d_in[4];
    const float* b2 = (const float*)d_in[5];
    float* out = (float*)d_out;

    const int* erow = ei;
    const int* ecol = ei + NE;

    // one-time host objects (created on the correctness call, before capture)
    static cudaStream_t s2 = nullptr;
    static cudaEvent_t evFork = nullptr, evJoin = nullptr;
    if (!s2) {
        cudaStreamCreateWithFlags(&s2, cudaStreamNonBlocking);
        cudaEventCreateWithFlags(&evFork, cudaEventDisableTiming);
        cudaEventCreateWithFlags(&evJoin, cudaEventDisableTiming);
        cudaFuncSetAttribute(k_gemm1_f16,
                             cudaFuncAttributeMaxDynamicSharedMemorySize, H1_SMEM_BYTES);
    }

    // ---- fork: graph prep on side stream (independent of GEMM1 chain)
    cudaEventRecord(evFork, 0);
    cudaStreamWaitEvent(s2, evFork, 0);
    k_init_deg<<<(NN + 255) / 256, 256, 0, s2>>>();
    k_count_deg<<<(NE + 255) / 256, 256, 0, s2>>>(ecol);
    k_scan_block<<<NSB, 512, 0, s2>>>();
    k_scan_finish2<<<(NN + 255) / 256, 256, 0, s2>>>();
    k_scatter<<<(NADJ + 255) / 256, 256, 0, s2>>>(erow, ecol);
    cudaEventRecord(evJoin, s2);

    // ---- main stream: fp16 conversion + layer 1 GEMM (overlaps prep)
    k_w1p<<<((DF / 2) * NH + 255) / 256, 256>>>(W1);
    k_xcvt<<<(int)(((size_t)NN * DF / 4 + 255) / 256), 256>>>(x);
    dim3 g1(NH / 128, (NN + 127) / 128);
    k_gemm1_f16<<<g1, 128, H1_SMEM_BYTES>>>();

    // ---- join: everything below needs prep outputs
    cudaStreamWaitEvent(0, evJoin, 0);

    k_agg1<<<NN, 128>>>(b1);
    k_gemm2_tf32<<<(NN + 127) / 128, 256>>>(W2);
    k_agg2<<<(NN + 7) / 8, 256>>>(b2, out);
}

// round 14
// speedup vs baseline: 1.6784x; 1.1352x over previous
#include <cuda_runtime.h>
#include <cuda_fp16.h>
#include <cuda_bf16.h>
#include <cstdint>

// Problem constants
#define NN 50000
#define NE 150000
#define DF 512
#define NH 512
#define NC 47
#define NADJ (NE + NN)
#define NSB 98   // (NN+511)/512

// ---------------- scratch (static __device__ — no allocation) ----------------
__device__ int   g_deg[NN];
__device__ __align__(16) float g_dinv[NN];
__device__ int   g_incl[NN];
__device__ int   g_bsum[128];
__device__ int   g_offs[NN + 1];
__device__ int   g_cursor[NN];
__device__ int   g_adj[NADJ];
__device__ __align__(16) __half   g_xh[(size_t)NN * DF];      // fp16 copy of x
__device__ __align__(16) uint32_t g_W1p[(DF / 2) * NH];       // W1 kpair-packed half2
__device__ __align__(16) uint32_t g_W2p[(NH / 2) * 64];       // W2 kpair-packed half2, cols padded to 64
__device__ __align__(16) __half g_h1h[(size_t)NN * NH];  // RAW x@W1 (fp16, no dinv)
__device__ __align__(16) __half g_a1h[(size_t)NN * NH];  // relu(agg1 + b1) fp16
__device__ __align__(16) float g_h2[(size_t)NN * NC];    // dinv-scaled layer2 pre-agg

// ---------------- graph prep ----------------
__global__ void k_init_deg() {
    int i = blockIdx.x * blockDim.x + threadIdx.x;
    if (i < NN) g_deg[i] = 1;  // self loop
}

__global__ void k_count_deg(const int* __restrict__ ecol) {
    int e = blockIdx.x * blockDim.x + threadIdx.x;
    if (e < NE) atomicAdd(&g_deg[ecol[e]], 1);
}

__global__ void k_scan_block() {
    __shared__ int s[512];
    int i = blockIdx.x * 512 + threadIdx.x;
    int v = (i < NN) ? g_deg[i] : 0;
    s[threadIdx.x] = v;
    __syncthreads();
    for (int off = 1; off < 512; off <<= 1) {
        int t = (threadIdx.x >= off) ? s[threadIdx.x - off] : 0;
        __syncthreads();
        s[threadIdx.x] += t;
        __syncthreads();
    }
    if (i < NN) g_incl[i] = s[threadIdx.x];
    if (threadIdx.x == 511) g_bsum[blockIdx.x] = s[511];
}

__global__ void k_scan_finish2() {
    __shared__ int sx[128];
    int t = threadIdx.x;
    int v = 0;
    if (t < 128) { v = (t < NSB) ? g_bsum[t] : 0; sx[t] = v; }
    __syncthreads();
    for (int off = 1; off < 128; off <<= 1) {
        int u = 0;
        if (t < 128 && t >= off) u = sx[t - off];
        __syncthreads();
        if (t < 128) sx[t] += u;
        __syncthreads();
    }
    if (t < 128) sx[t] -= v;   // exclusive
    __syncthreads();
    int i = blockIdx.x * blockDim.x + t;
    if (i < NN) {
        int e = g_incl[i] - g_deg[i] + sx[i >> 9];
        g_offs[i] = e;
        g_cursor[i] = e;
        g_dinv[i] = rsqrtf((float)g_deg[i]);
    }
    if (i == 0) g_offs[NN] = NADJ;
}

__global__ void k_scatter(const int* __restrict__ erow,
                          const int* __restrict__ ecol) {
    int t = blockIdx.x * blockDim.x + threadIdx.x;
    if (t < NE) {
        int c = ecol[t];
        int p = atomicAdd(&g_cursor[c], 1);
        g_adj[p] = erow[t];
    } else if (t < NADJ) {
        int i = t - NE;
        int p = atomicAdd(&g_cursor[i], 1);
        g_adj[p] = i;
    }
}

// ---------------- conversions ----------------
__global__ void k_xcvt(const float* __restrict__ x) {
    size_t i = (size_t)blockIdx.x * 256 + threadIdx.x;   // float4 index
    if (i < (size_t)NN * DF / 4) {
        float4 v = __ldg((const float4*)x + i);
        __half2 h0 = __float22half2_rn(make_float2(v.x, v.y));
        __half2 h1 = __float22half2_rn(make_float2(v.z, v.w));
        uint2 o;
        o.x = *(uint32_t*)&h0;
        o.y = *(uint32_t*)&h1;
        *((uint2*)g_xh + i) = o;
    }
}

__global__ void k_w1p(const float* __restrict__ W1) {
    int i = blockIdx.x * 256 + threadIdx.x;   // word index
    if (i < (DF / 2) * NH) {
        int kp = i >> 9;
        int n = i & (NH - 1);
        float lo = __ldg(W1 + (size_t)(2 * kp) * NH + n);
        float hi = __ldg(W1 + (size_t)(2 * kp + 1) * NH + n);
        __half2 h = __float22half2_rn(make_float2(lo, hi));
        g_W1p[i] = *(uint32_t*)&h;
    }
}

__global__ void k_w2p(const float* __restrict__ W2) {
    int i = blockIdx.x * 256 + threadIdx.x;   // word index
    if (i < (NH / 2) * 64) {
        int kp = i >> 6;       // 0..255
        int n = i & 63;
        float lo = (n < NC) ? __ldg(W2 + (size_t)(2 * kp) * NC + n) : 0.f;
        float hi = (n < NC) ? __ldg(W2 + (size_t)(2 * kp + 1) * NC + n) : 0.f;
        __half2 h = __float22half2_rn(make_float2(lo, hi));
        g_W2p[i] = *(uint32_t*)&h;
    }
}

// ---------------- helpers ----------------
__device__ __forceinline__ void mma_f16(float& c0, float& c1, float& c2, float& c3,
                                        uint32_t a0, uint32_t a1, uint32_t a2, uint32_t a3,
                                        uint32_t b0, uint32_t b1) {
    asm volatile(
        "mma.sync.aligned.m16n8k16.row.col.f32.f16.f16.f32 "
        "{%0,%1,%2,%3},{%4,%5,%6,%7},{%8,%9},{%0,%1,%2,%3};"
        : "+f"(c0), "+f"(c1), "+f"(c2), "+f"(c3)
        : "r"(a0), "r"(a1), "r"(a2), "r"(a3), "r"(b0), "r"(b1));
}

__device__ __forceinline__ void cp16(uint32_t dst_smem, const void* src, bool pred) {
    int sz = pred ? 16 : 0;
    asm volatile("cp.async.cg.shared.global [%0], [%1], 16, %2;\n"
                 :: "r"(dst_smem), "l"(src), "r"(sz));
}

// ---------------- GEMM1 (FP16 HMMA, 2-stage cp.async pipeline) ----------------
// g_h1h[m,f] = (half) sum_k xh[m,k] * W1[k,f]
// BM=128, BN=128, BK=32; 128 threads = 4 warps (2M x 2N); warp tile 64x64.
#define H1_ASTRIDE 20
#define H1_AELEMS (128 * H1_ASTRIDE)
#define H1_BSTRIDE 136
#define H1_STAGE  (H1_AELEMS + 16 * H1_BSTRIDE)
#define H1_SMEM_BYTES (2 * H1_STAGE * 4)

__global__ __launch_bounds__(128) void k_gemm1_f16() {
    extern __shared__ __align__(16) uint32_t dynsm[];

    const int tid = threadIdx.x;
    const int lane = tid & 31;
    const int warp = tid >> 5;
    const int wm = warp & 1;
    const int wn = warp >> 1;
    const int gp = lane >> 2;
    const int tq = lane & 3;

    const int rowBase = blockIdx.y * 128;
    const int colBase = blockIdx.x * 128;
    const int warpRow = wm * 64;
    const int warpCol = wn * 64;

    uint32_t smem_u32 = (uint32_t)__cvta_generic_to_shared((void*)dynsm);

    float acc[4][8][4];
#pragma unroll
    for (int mi = 0; mi < 4; mi++)
#pragma unroll
        for (int ni = 0; ni < 8; ni++)
#pragma unroll
            for (int j = 0; j < 4; j++) acc[mi][ni][j] = 0.f;

    const int NT = DF / 32;

    auto load_stage = [&](int st, int t) {
        uint32_t aBase = smem_u32 + (uint32_t)(st * H1_STAGE) * 4u;
        uint32_t bBase = aBase + (uint32_t)H1_AELEMS * 4u;
#pragma unroll
        for (int i = 0; i < 4; i++) {
            int fid = tid + i * 128;
            int r = fid >> 2, q = fid & 3;
            int gr = rowBase + r;
            bool ok = gr < NN;
            const __half* src = g_xh + (size_t)(ok ? gr : 0) * DF + t * 32 + q * 8;
            cp16(aBase + (uint32_t)(r * H1_ASTRIDE + q * 4) * 4u, src, ok);
        }
#pragma unroll
        for (int i = 0; i < 4; i++) {
            int fid = tid + i * 128;
            int r = fid >> 5, q = fid & 31;
            const uint32_t* src = g_W1p + (size_t)(t * 16 + r) * NH + colBase + q * 4;
            cp16(bBase + (uint32_t)(r * H1_BSTRIDE + q * 4) * 4u, src, true);
        }
    };

    load_stage(0, 0);
    asm volatile("cp.async.commit_group;\n");

    for (int t = 0; t < NT; t++) {
        if (t + 1 < NT) load_stage((t + 1) & 1, t + 1);
        asm volatile("cp.async.commit_group;\n");
        if (t + 1 < NT) asm volatile("cp.async.wait_group 1;\n");
        else            asm volatile("cp.async.wait_group 0;\n");
        __syncthreads();

        const uint32_t* AsS = dynsm + (t & 1) * H1_STAGE;
        const uint32_t* BsS = AsS + H1_AELEMS;

#pragma unroll
        for (int kk2 = 0; kk2 < 16; kk2 += 8) {
            uint32_t a[4][4];
#pragma unroll
            for (int mi = 0; mi < 4; mi++) {
                int r0 = warpRow + mi * 16 + gp;
                a[mi][0] = AsS[r0 * H1_ASTRIDE + kk2 + tq];
                a[mi][1] = AsS[(r0 + 8) * H1_ASTRIDE + kk2 + tq];
                a[mi][2] = AsS[r0 * H1_ASTRIDE + kk2 + tq + 4];
                a[mi][3] = AsS[(r0 + 8) * H1_ASTRIDE + kk2 + tq + 4];
            }
            uint32_t b[8][2];
#pragma unroll
            for (int ni = 0; ni < 8; ni++) {
                int c = warpCol + ni * 8 + gp;
                b[ni][0] = BsS[(kk2 + tq) * H1_BSTRIDE + c];
                b[ni][1] = BsS[(kk2 + tq + 4) * H1_BSTRIDE + c];
            }
#pragma unroll
            for (int mi = 0; mi < 4; mi++)
#pragma unroll
                for (int ni = 0; ni < 8; ni++)
                    mma_f16(acc[mi][ni][0], acc[mi][ni][1],
                            acc[mi][ni][2], acc[mi][ni][3],
                            a[mi][0], a[mi][1], a[mi][2], a[mi][3],
                            b[ni][0], b[ni][1]);
        }
        __syncthreads();
    }

#pragma unroll
    for (int mi = 0; mi < 4; mi++) {
        int r0 = rowBase + warpRow + mi * 16 + gp;
        int r1 = r0 + 8;
#pragma unroll
        for (int ni = 0; ni < 8; ni++) {
            int c = colBase + warpCol + ni * 8 + tq * 2;
            if (r0 < NN) {
                __half2 o = __float22half2_rn(make_float2(acc[mi][ni][0], acc[mi][ni][1]));
                *(__half2*)(g_h1h + (size_t)r0 * NH + c) = o;
            }
            if (r1 < NN) {
                __half2 o = __float22half2_rn(make_float2(acc[mi][ni][2], acc[mi][ni][3]));
                *(__half2*)(g_h1h + (size_t)r1 * NH + c) = o;
            }
        }
    }
}

// ---------------- agg1: a1[i,f] = relu(dinv[i]*sum_{adj} dinv[r]*h1[r,f] + b1[f]) --------
// output fp16
__global__ __launch_bounds__(128) void k_agg1(const float* __restrict__ b1) {
    const int node = blockIdx.x;
    const int f = threadIdx.x * 4;
    const int s = g_offs[node], e = g_offs[node + 1];
    float4 acc = make_float4(0.f, 0.f, 0.f, 0.f);
    for (int p = s; p < e; p++) {
        int r = g_adj[p];
        float dr = __ldg(&g_dinv[r]);
        uint2 raw = *(const uint2*)(g_h1h + (size_t)r * NH + f);
        __half2 h01 = *(__half2*)&raw.x;
        __half2 h23 = *(__half2*)&raw.y;
        float2 v01 = __half22float2(h01);
        float2 v23 = __half22float2(h23);
        acc.x += dr * v01.x; acc.y += dr * v01.y;
        acc.z += dr * v23.x; acc.w += dr * v23.y;
    }
    float d = g_dinv[node];
    float4 bb = *(const float4*)(b1 + f);
    float4 o;
    o.x = fmaxf(d * acc.x + bb.x, 0.f);
    o.y = fmaxf(d * acc.y + bb.y, 0.f);
    o.z = fmaxf(d * acc.z + bb.z, 0.f);
    o.w = fmaxf(d * acc.w + bb.w, 0.f);
    __half2 h01 = __float22half2_rn(make_float2(o.x, o.y));
    __half2 h23 = __float22half2_rn(make_float2(o.z, o.w));
    uint2 ou;
    ou.x = *(uint32_t*)&h01;
    ou.y = *(uint32_t*)&h23;
    *(uint2*)(g_a1h + (size_t)node * NH + f) = ou;
}

// ---------------- GEMM2 (FP16 HMMA, 2-stage cp.async pipeline) ----------------
// g_h2[m,c] = dinv[m] * sum_k a1h[m,k] * W2[k,c]
// BM=128, BN=64 (guarded to 47), BK=32; 256 threads = 8 warps (4M x 2N); warp tile 32x32.
#define H2_ASTRIDE 20
#define H2_AELEMS (128 * H2_ASTRIDE)                // 2560 words
#define H2_BSTRIDE 72
#define H2_STAGE  (H2_AELEMS + 16 * H2_BSTRIDE)     // 3712 words
#define H2_SMEM_BYTES (2 * H2_STAGE * 4)            // 29696 B

__global__ __launch_bounds__(256) void k_gemm2_f16() {
    extern __shared__ __align__(16) uint32_t dynsm[];

    const int tid = threadIdx.x;
    const int lane = tid & 31;
    const int warp = tid >> 5;        // 0..7
    const int wm = warp & 3;
    const int wn = warp >> 2;
    const int gp = lane >> 2;
    const int tq = lane & 3;

    const int rowBase = blockIdx.x * 128;
    const int warpRow = wm * 32;
    const int warpCol = wn * 32;

    uint32_t smem_u32 = (uint32_t)__cvta_generic_to_shared((void*)dynsm);

    float acc[2][4][4];
#pragma unroll
    for (int mi = 0; mi < 2; mi++)
#pragma unroll
        for (int ni = 0; ni < 4; ni++)
#pragma unroll
            for (int j = 0; j < 4; j++) acc[mi][ni][j] = 0.f;

    const int NT = NH / 32;   // 16 k-tiles

    auto load_stage = [&](int st, int t) {
        uint32_t aBase = smem_u32 + (uint32_t)(st * H2_STAGE) * 4u;
        uint32_t bBase = aBase + (uint32_t)H2_AELEMS * 4u;
        // A: 128 rows x 64 B = 512 chunks -> 2/thread
#pragma unroll
        for (int i = 0; i < 2; i++) {
            int fid = tid + i * 256;
            int r = fid >> 2, q = fid & 3;
            int gr = rowBase + r;
            bool ok = gr < NN;
            const __half* src = g_a1h + (size_t)(ok ? gr : 0) * NH + t * 32 + q * 8;
            cp16(aBase + (uint32_t)(r * H2_ASTRIDE + q * 4) * 4u, src, ok);
        }
        // B: 16 kpair rows x 256 B (64 words) = 256 chunks -> 1/thread
        {
            int r = tid >> 4, q = tid & 15;   // r 0..15, q 0..15 (16B chunks of 64 words)
            const uint32_t* src = g_W2p + (size_t)(t * 16 + r) * 64 + q * 4;
            cp16(bBase + (uint32_t)(r * H2_BSTRIDE + q * 4) * 4u, src, true);
        }
    };

    load_stage(0, 0);
    asm volatile("cp.async.commit_group;\n");

    for (int t = 0; t < NT; t++) {
        if (t + 1 < NT) load_stage((t + 1) & 1, t + 1);
        asm volatile("cp.async.commit_group;\n");
        if (t + 1 < NT) asm volatile("cp.async.wait_group 1;\n");
        else            asm volatile("cp.async.wait_group 0;\n");
        __syncthreads();

        const uint32_t* AsS = dynsm + (t & 1) * H2_STAGE;
        const uint32_t* BsS = AsS + H2_AELEMS;

#pragma unroll
        for (int kk2 = 0; kk2 < 16; kk2 += 8) {
            uint32_t a[2][4];
#pragma unroll
            for (int mi = 0; mi < 2; mi++) {
                int r0 = warpRow + mi * 16 + gp;
                a[mi][0] = AsS[r0 * H2_ASTRIDE + kk2 + tq];
                a[mi][1] = AsS[(r0 + 8) * H2_ASTRIDE + kk2 + tq];
                a[mi][2] = AsS[r0 * H2_ASTRIDE + kk2 + tq + 4];
                a[mi][3] = AsS[(r0 + 8) * H2_ASTRIDE + kk2 + tq + 4];
            }
            uint32_t b[4][2];
#pragma unroll
            for (int ni = 0; ni < 4; ni++) {
                int c = warpCol + ni * 8 + gp;   // 0..63 < 72
                b[ni][0] = BsS[(kk2 + tq) * H2_BSTRIDE + c];
                b[ni][1] = BsS[(kk2 + tq + 4) * H2_BSTRIDE + c];
            }
#pragma unroll
            for (int mi = 0; mi < 2; mi++)
#pragma unroll
                for (int ni = 0; ni < 4; ni++)
                    mma_f16(acc[mi][ni][0], acc[mi][ni][1],
                            acc[mi][ni][2], acc[mi][ni][3],
                            a[mi][0], a[mi][1], a[mi][2], a[mi][3],
                            b[ni][0], b[ni][1]);
        }
        __syncthreads();
    }

    // ---- epilogue with N guard
#pragma unroll
    for (int mi = 0; mi < 2; mi++) {
        int r0 = rowBase + warpRow + mi * 16 + gp;
        int r1 = r0 + 8;
        float d0 = (r0 < NN) ? g_dinv[r0] : 0.f;
        float d1 = (r1 < NN) ? g_dinv[r1] : 0.f;
#pragma unroll
        for (int ni = 0; ni < 4; ni++) {
            int c = warpCol + ni * 8 + tq * 2;
            if (r0 < NN) {
                if (c < NC)     g_h2[(size_t)r0 * NC + c]     = d0 * acc[mi][ni][0];
                if (c + 1 < NC) g_h2[(size_t)r0 * NC + c + 1] = d0 * acc[mi][ni][1];
            }
            if (r1 < NN) {
                if (c < NC)     g_h2[(size_t)r1 * NC + c]     = d1 * acc[mi][ni][2];
                if (c + 1 < NC) g_h2[(size_t)r1 * NC + c + 1] = d1 * acc[mi][ni][3];
            }
        }
    }
}

// ---------------- agg2: out[i,c] = dinv[i]*sum_{adj} h2[row,c] + b2[c] ----------------
__global__ __launch_bounds__(256) void k_agg2(const float* __restrict__ b2,
                                              float* __restrict__ out) {
    int node = blockIdx.x * 8 + (threadIdx.x >> 5);
    if (node >= NN) return;
    int lane = threadIdx.x & 31;
    int s = g_offs[node], e = g_offs[node + 1];
    float a0 = 0.f, a1 = 0.f;
    for (int p = s; p < e; p++) {
        int r = g_adj[p];
        const float* gp = g_h2 + (size_t)r * NC;
        a0 += gp[lane];
        if (lane + 32 < NC) a1 += gp[lane + 32];
    }
    float d = g_dinv[node];
    out[(size_t)node * NC + lane] = d * a0 + b2[lane];
    if (lane + 32 < NC)
        out[(size_t)node * NC + lane + 32] = d * a1 + b2[lane + 32];
}

// ---------------- launch ----------------
extern "C" void kernel_launch(void* const* d_in, const int* in_sizes, int n_in,
                              void* d_out, int out_size) {
    const float* x  = (const float*)d_in[0];
    const int*   ei = (const int*)d_in[1];   // [2, NE] int32
    const float* W1 = (const float*)d_in[2];
    const float* b1 = (const float*)d_in[3];
    const float* W2 = (const float*)d_in[4];
    const float* b2 = (const float*)d_in[5];
    float* out = (float*)d_out;

    const int* erow = ei;
    const int* ecol = ei + NE;

    // one-time host objects (created on the correctness call, before capture)
    static cudaStream_t s2 = nullptr;
    static cudaEvent_t evFork = nullptr, evJoin = nullptr;
    if (!s2) {
        cudaStreamCreateWithFlags(&s2, cudaStreamNonBlocking);
        cudaEventCreateWithFlags(&evFork, cudaEventDisableTiming);
        cudaEventCreateWithFlags(&evJoin, cudaEventDisableTiming);
        cudaFuncSetAttribute(k_gemm1_f16,
                             cudaFuncAttributeMaxDynamicSharedMemorySize, H1_SMEM_BYTES);
        cudaFuncSetAttribute(k_gemm2_f16,
                             cudaFuncAttributeMaxDynamicSharedMemorySize, H2_SMEM_BYTES);
    }

    // ---- fork: graph prep + W2 pack on side stream
    cudaEventRecord(evFork, 0);
    cudaStreamWaitEvent(s2, evFork, 0);
    k_w2p<<<((NH / 2) * 64 + 255) / 256, 256, 0, s2>>>(W2);
    k_init_deg<<<(NN + 255) / 256, 256, 0, s2>>>();
    k_count_deg<<<(NE + 255) / 256, 256, 0, s2>>>(ecol);
    k_scan_block<<<NSB, 512, 0, s2>>>();
    k_scan_finish2<<<(NN + 255) / 256, 256, 0, s2>>>();
    k_scatter<<<(NADJ + 255) / 256, 256, 0, s2>>>(erow, ecol);
    cudaEventRecord(evJoin, s2);

    // ---- main stream: fp16 conversion + layer 1 GEMM (overlaps prep)
    k_w1p<<<((DF / 2) * NH + 255) / 256, 256>>>(W1);
    k_xcvt<<<(int)(((size_t)NN * DF / 4 + 255) / 256), 256>>>(x);
    dim3 g1(NH / 128, (NN + 127) / 128);
    k_gemm1_f16<<<g1, 128, H1_SMEM_BYTES>>>();

    // ---- join: everything below needs prep outputs
    cudaStreamWaitEvent(0, evJoin, 0);

    k_agg1<<<NN, 128>>>(b1);
    k_gemm2_f16<<<(NN + 127) / 128, 256, H2_SMEM_BYTES>>>();
    k_agg2<<<(NN + 7) / 8, 256>>>(b2, out);
}

// round 15
// speedup vs baseline: 1.8803x; 1.1203x over previous
#include <cuda_runtime.h>
#include <cuda_fp16.h>
#include <cuda_bf16.h>
#include <cstdint>

// Problem constants
#define NN 50000
#define NE 150000
#define DF 512
#define NH 512
#define NC 47
#define NADJ (NE + NN)
#define NSB 98   // (NN+511)/512

// ---------------- scratch (static __device__ — no allocation) ----------------
__device__ int   g_deg[NN];
__device__ __align__(16) float g_dinv[NN];
__device__ int   g_incl[NN];
__device__ int   g_bsum[128];
__device__ int   g_offs[NN + 1];
__device__ int   g_cursor[NN];
__device__ int   g_adj[NADJ];
__device__ __align__(16) uint32_t g_W1p[(DF / 2) * NH];       // W1 kpair-packed half2
__device__ __align__(16) uint32_t g_W2p[(NH / 2) * 64];       // W2 kpair-packed half2, cols padded to 64
__device__ __align__(16) __half g_h1h[(size_t)NN * NH];  // RAW x@W1 (fp16, no dinv)
__device__ __align__(16) __half g_a1h[(size_t)NN * NH];  // relu(agg1 + b1) fp16
__device__ __align__(16) float g_h2[(size_t)NN * NC];    // dinv-scaled layer2 pre-agg

// ---------------- graph prep ----------------
__global__ void k_init_deg() {
    int i = blockIdx.x * blockDim.x + threadIdx.x;
    if (i < NN) g_deg[i] = 1;  // self loop
}

__global__ void k_count_deg(const int* __restrict__ ecol) {
    int e = blockIdx.x * blockDim.x + threadIdx.x;
    if (e < NE) atomicAdd(&g_deg[ecol[e]], 1);
}

__global__ void k_scan_block() {
    __shared__ int s[512];
    int i = blockIdx.x * 512 + threadIdx.x;
    int v = (i < NN) ? g_deg[i] : 0;
    s[threadIdx.x] = v;
    __syncthreads();
    for (int off = 1; off < 512; off <<= 1) {
        int t = (threadIdx.x >= off) ? s[threadIdx.x - off] : 0;
        __syncthreads();
        s[threadIdx.x] += t;
        __syncthreads();
    }
    if (i < NN) g_incl[i] = s[threadIdx.x];
    if (threadIdx.x == 511) g_bsum[blockIdx.x] = s[511];
}

__global__ void k_scan_finish2() {
    __shared__ int sx[128];
    int t = threadIdx.x;
    int v = 0;
    if (t < 128) { v = (t < NSB) ? g_bsum[t] : 0; sx[t] = v; }
    __syncthreads();
    for (int off = 1; off < 128; off <<= 1) {
        int u = 0;
        if (t < 128 && t >= off) u = sx[t - off];
        __syncthreads();
        if (t < 128) sx[t] += u;
        __syncthreads();
    }
    if (t < 128) sx[t] -= v;   // exclusive
    __syncthreads();
    int i = blockIdx.x * blockDim.x + t;
    if (i < NN) {
        int e = g_incl[i] - g_deg[i] + sx[i >> 9];
        g_offs[i] = e;
        g_cursor[i] = e;
        g_dinv[i] = rsqrtf((float)g_deg[i]);
    }
    if (i == 0) g_offs[NN] = NADJ;
}

__global__ void k_scatter(const int* __restrict__ erow,
                          const int* __restrict__ ecol) {
    int t = blockIdx.x * blockDim.x + threadIdx.x;
    if (t < NE) {
        int c = ecol[t];
        int p = atomicAdd(&g_cursor[c], 1);
        g_adj[p] = erow[t];
    } else if (t < NADJ) {
        int i = t - NE;
        int p = atomicAdd(&g_cursor[i], 1);
        g_adj[p] = i;
    }
}

// ---------------- conversions ----------------
__global__ void k_w1p(const float* __restrict__ W1) {
    int i = blockIdx.x * 256 + threadIdx.x;   // word index
    if (i < (DF / 2) * NH) {
        int kp = i >> 9;
        int n = i & (NH - 1);
        float lo = __ldg(W1 + (size_t)(2 * kp) * NH + n);
        float hi = __ldg(W1 + (size_t)(2 * kp + 1) * NH + n);
        __half2 h = __float22half2_rn(make_float2(lo, hi));
        g_W1p[i] = *(uint32_t*)&h;
    }
}

__global__ void k_w2p(const float* __restrict__ W2) {
    int i = blockIdx.x * 256 + threadIdx.x;   // word index
    if (i < (NH / 2) * 64) {
        int kp = i >> 6;       // 0..255
        int n = i & 63;
        float lo = (n < NC) ? __ldg(W2 + (size_t)(2 * kp) * NC + n) : 0.f;
        float hi = (n < NC) ? __ldg(W2 + (size_t)(2 * kp + 1) * NC + n) : 0.f;
        __half2 h = __float22half2_rn(make_float2(lo, hi));
        g_W2p[i] = *(uint32_t*)&h;
    }
}

// ---------------- helpers ----------------
__device__ __forceinline__ void mma_f16(float& c0, float& c1, float& c2, float& c3,
                                        uint32_t a0, uint32_t a1, uint32_t a2, uint32_t a3,
                                        uint32_t b0, uint32_t b1) {
    asm volatile(
        "mma.sync.aligned.m16n8k16.row.col.f32.f16.f16.f32 "
        "{%0,%1,%2,%3},{%4,%5,%6,%7},{%8,%9},{%0,%1,%2,%3};"
        : "+f"(c0), "+f"(c1), "+f"(c2), "+f"(c3)
        : "r"(a0), "r"(a1), "r"(a2), "r"(a3), "r"(b0), "r"(b1));
}

__device__ __forceinline__ void cp16(uint32_t dst_smem, const void* src, bool pred) {
    int sz = pred ? 16 : 0;
    asm volatile("cp.async.cg.shared.global [%0], [%1], 16, %2;\n"
                 :: "r"(dst_smem), "l"(src), "r"(sz));
}

// pack 2 consecutive fp32 SMEM words into one half2 register
__device__ __forceinline__ uint32_t pack_h2(const uint32_t* base, int widx) {
    float2 v = *(const float2*)(base + widx);   // LDS.64, widx even
    __half2 h = __float22half2_rn(v);
    return *(uint32_t*)&h;
}

// ---------------- GEMM1 (FP16 HMMA, fp32-A inline convert, 2-stage cp.async) ----------
// g_h1h[m,f] = (half) sum_k x[m,k] * W1[k,f]    (x converted to fp16 at fragment load)
// BM=128, BN=128, BK=32; 128 threads = 4 warps (2M x 2N); warp tile 64x64.
// A stage: [128 rows][32 k fp32 words] stride 40 (LDS.64 bank-pairs optimal)
// B stage: [16 kpair rows][128 n half2 words] stride 136
#define H1_ASTRIDE 40
#define H1_AELEMS (128 * H1_ASTRIDE)                // 5120 words
#define H1_BSTRIDE 136
#define H1_STAGE  (H1_AELEMS + 16 * H1_BSTRIDE)     // 7296 words
#define H1_SMEM_BYTES (2 * H1_STAGE * 4)            // 58368 B

__global__ __launch_bounds__(128) void k_gemm1_f16(const float* __restrict__ x) {
    extern __shared__ __align__(16) uint32_t dynsm[];

    const int tid = threadIdx.x;
    const int lane = tid & 31;
    const int warp = tid >> 5;
    const int wm = warp & 1;
    const int wn = warp >> 1;
    const int gp = lane >> 2;
    const int tq = lane & 3;

    const int rowBase = blockIdx.y * 128;
    const int colBase = blockIdx.x * 128;
    const int warpRow = wm * 64;
    const int warpCol = wn * 64;

    uint32_t smem_u32 = (uint32_t)__cvta_generic_to_shared((void*)dynsm);

    float acc[4][8][4];
#pragma unroll
    for (int mi = 0; mi < 4; mi++)
#pragma unroll
        for (int ni = 0; ni < 8; ni++)
#pragma unroll
            for (int j = 0; j < 4; j++) acc[mi][ni][j] = 0.f;

    const int NT = DF / 32;

    auto load_stage = [&](int st, int t) {
        uint32_t aBase = smem_u32 + (uint32_t)(st * H1_STAGE) * 4u;
        uint32_t bBase = aBase + (uint32_t)H1_AELEMS * 4u;
        // A: 128 rows x 128 B (32 fp32) = 1024 chunks of 16B -> 8/thread
#pragma unroll
        for (int i = 0; i < 8; i++) {
            int fid = tid + i * 128;
            int r = fid >> 3, q = fid & 7;
            int gr = rowBase + r;
            bool ok = gr < NN;
            const float* src = x + (size_t)(ok ? gr : 0) * DF + t * 32 + q * 4;
            cp16(aBase + (uint32_t)(r * H1_ASTRIDE + q * 4) * 4u, src, ok);
        }
        // B: 16 kpair rows x 512 B (128 words) = 512 chunks -> 4/thread
#pragma unroll
        for (int i = 0; i < 4; i++) {
            int fid = tid + i * 128;
            int r = fid >> 5, q = fid & 31;
            const uint32_t* src = g_W1p + (size_t)(t * 16 + r) * NH + colBase + q * 4;
            cp16(bBase + (uint32_t)(r * H1_BSTRIDE + q * 4) * 4u, src, true);
        }
    };

    load_stage(0, 0);
    asm volatile("cp.async.commit_group;\n");

    for (int t = 0; t < NT; t++) {
        if (t + 1 < NT) load_stage((t + 1) & 1, t + 1);
        asm volatile("cp.async.commit_group;\n");
        if (t + 1 < NT) asm volatile("cp.async.wait_group 1;\n");
        else            asm volatile("cp.async.wait_group 0;\n");
        __syncthreads();

        const uint32_t* AsS = dynsm + (t & 1) * H1_STAGE;
        const uint32_t* BsS = AsS + H1_AELEMS;

#pragma unroll
        for (int kk2 = 0; kk2 < 16; kk2 += 8) {
            uint32_t a[4][4];
#pragma unroll
            for (int mi = 0; mi < 4; mi++) {
                int r0 = warpRow + mi * 16 + gp;
                int w0 = 2 * (kk2 + tq);
                int w1 = 2 * (kk2 + tq + 4);
                a[mi][0] = pack_h2(AsS, r0 * H1_ASTRIDE + w0);
                a[mi][1] = pack_h2(AsS, (r0 + 8) * H1_ASTRIDE + w0);
                a[mi][2] = pack_h2(AsS, r0 * H1_ASTRIDE + w1);
                a[mi][3] = pack_h2(AsS, (r0 + 8) * H1_ASTRIDE + w1);
            }
            uint32_t b[8][2];
#pragma unroll
            for (int ni = 0; ni < 8; ni++) {
                int c = warpCol + ni * 8 + gp;
                b[ni][0] = BsS[(kk2 + tq) * H1_BSTRIDE + c];
                b[ni][1] = BsS[(kk2 + tq + 4) * H1_BSTRIDE + c];
            }
#pragma unroll
            for (int mi = 0; mi < 4; mi++)
#pragma unroll
                for (int ni = 0; ni < 8; ni++)
                    mma_f16(acc[mi][ni][0], acc[mi][ni][1],
                            acc[mi][ni][2], acc[mi][ni][3],
                            a[mi][0], a[mi][1], a[mi][2], a[mi][3],
                            b[ni][0], b[ni][1]);
        }
        __syncthreads();
    }

#pragma unroll
    for (int mi = 0; mi < 4; mi++) {
        int r0 = rowBase + warpRow + mi * 16 + gp;
        int r1 = r0 + 8;
#pragma unroll
        for (int ni = 0; ni < 8; ni++) {
            int c = colBase + warpCol + ni * 8 + tq * 2;
            if (r0 < NN) {
                __half2 o = __float22half2_rn(make_float2(acc[mi][ni][0], acc[mi][ni][1]));
                *(__half2*)(g_h1h + (size_t)r0 * NH + c) = o;
            }
            if (r1 < NN) {
                __half2 o = __float22half2_rn(make_float2(acc[mi][ni][2], acc[mi][ni][3]));
                *(__half2*)(g_h1h + (size_t)r1 * NH + c) = o;
            }
        }
    }
}

// ---------------- agg1: a1[i,f] = relu(dinv[i]*sum_{adj} dinv[r]*h1[r,f] + b1[f]) --------
// output fp16
__global__ __launch_bounds__(128) void k_agg1(const float* __restrict__ b1) {
    const int node = blockIdx.x;
    const int f = threadIdx.x * 4;
    const int s = g_offs[node], e = g_offs[node + 1];
    float4 acc = make_float4(0.f, 0.f, 0.f, 0.f);
    for (int p = s; p < e; p++) {
        int r = g_adj[p];
        float dr = __ldg(&g_dinv[r]);
        uint2 raw = *(const uint2*)(g_h1h + (size_t)r * NH + f);
        __half2 h01 = *(__half2*)&raw.x;
        __half2 h23 = *(__half2*)&raw.y;
        float2 v01 = __half22float2(h01);
        float2 v23 = __half22float2(h23);
        acc.x += dr * v01.x; acc.y += dr * v01.y;
        acc.z += dr * v23.x; acc.w += dr * v23.y;
    }
    float d = g_dinv[node];
    float4 bb = *(const float4*)(b1 + f);
    float4 o;
    o.x = fmaxf(d * acc.x + bb.x, 0.f);
    o.y = fmaxf(d * acc.y + bb.y, 0.f);
    o.z = fmaxf(d * acc.z + bb.z, 0.f);
    o.w = fmaxf(d * acc.w + bb.w, 0.f);
    __half2 h01 = __float22half2_rn(make_float2(o.x, o.y));
    __half2 h23 = __float22half2_rn(make_float2(o.z, o.w));
    uint2 ou;
    ou.x = *(uint32_t*)&h01;
    ou.y = *(uint32_t*)&h23;
    *(uint2*)(g_a1h + (size_t)node * NH + f) = ou;
}

// ---------------- GEMM2 (FP16 HMMA, 2-stage cp.async pipeline) ----------------
// g_h2[m,c] = dinv[m] * sum_k a1h[m,k] * W2[k,c]
// BM=128, BN=64 (guarded to 47), BK=32; 256 threads = 8 warps (4M x 2N); warp tile 32x32.
#define H2_ASTRIDE 20
#define H2_AELEMS (128 * H2_ASTRIDE)
#define H2_BSTRIDE 72
#define H2_STAGE  (H2_AELEMS + 16 * H2_BSTRIDE)
#define H2_SMEM_BYTES (2 * H2_STAGE * 4)

__global__ __launch_bounds__(256) void k_gemm2_f16() {
    extern __shared__ __align__(16) uint32_t dynsm[];

    const int tid = threadIdx.x;
    const int lane = tid & 31;
    const int warp = tid >> 5;
    const int wm = warp & 3;
    const int wn = warp >> 2;
    const int gp = lane >> 2;
    const int tq = lane & 3;

    const int rowBase = blockIdx.x * 128;
    const int warpRow = wm * 32;
    const int warpCol = wn * 32;

    uint32_t smem_u32 = (uint32_t)__cvta_generic_to_shared((void*)dynsm);

    float acc[2][4][4];
#pragma unroll
    for (int mi = 0; mi < 2; mi++)
#pragma unroll
        for (int ni = 0; ni < 4; ni++)
#pragma unroll
            for (int j = 0; j < 4; j++) acc[mi][ni][j] = 0.f;

    const int NT = NH / 32;

    auto load_stage = [&](int st, int t) {
        uint32_t aBase = smem_u32 + (uint32_t)(st * H2_STAGE) * 4u;
        uint32_t bBase = aBase + (uint32_t)H2_AELEMS * 4u;
#pragma unroll
        for (int i = 0; i < 2; i++) {
            int fid = tid + i * 256;
            int r = fid >> 2, q = fid & 3;
            int gr = rowBase + r;
            bool ok = gr < NN;
            const __half* src = g_a1h + (size_t)(ok ? gr : 0) * NH + t * 32 + q * 8;
            cp16(aBase + (uint32_t)(r * H2_ASTRIDE + q * 4) * 4u, src, ok);
        }
        {
            int r = tid >> 4, q = tid & 15;
            const uint32_t* src = g_W2p + (size_t)(t * 16 + r) * 64 + q * 4;
            cp16(bBase + (uint32_t)(r * H2_BSTRIDE + q * 4) * 4u, src, true);
        }
    };

    load_stage(0, 0);
    asm volatile("cp.async.commit_group;\n");

    for (int t = 0; t < NT; t++) {
        if (t + 1 < NT) load_stage((t + 1) & 1, t + 1);
        asm volatile("cp.async.commit_group;\n");
        if (t + 1 < NT) asm volatile("cp.async.wait_group 1;\n");
        else            asm volatile("cp.async.wait_group 0;\n");
        __syncthreads();

        const uint32_t* AsS = dynsm + (t & 1) * H2_STAGE;
        const uint32_t* BsS = AsS + H2_AELEMS;

#pragma unroll
        for (int kk2 = 0; kk2 < 16; kk2 += 8) {
            uint32_t a[2][4];
#pragma unroll
            for (int mi = 0; mi < 2; mi++) {
                int r0 = warpRow + mi * 16 + gp;
                a[mi][0] = AsS[r0 * H2_ASTRIDE + kk2 + tq];
                a[mi][1] = AsS[(r0 + 8) * H2_ASTRIDE + kk2 + tq];
                a[mi][2] = AsS[r0 * H2_ASTRIDE + kk2 + tq + 4];
                a[mi][3] = AsS[(r0 + 8) * H2_ASTRIDE + kk2 + tq + 4];
            }
            uint32_t b[4][2];
#pragma unroll
            for (int ni = 0; ni < 4; ni++) {
                int c = warpCol + ni * 8 + gp;
                b[ni][0] = BsS[(kk2 + tq) * H2_BSTRIDE + c];
                b[ni][1] = BsS[(kk2 + tq + 4) * H2_BSTRIDE + c];
            }
#pragma unroll
            for (int mi = 0; mi < 2; mi++)
#pragma unroll
                for (int ni = 0; ni < 4; ni++)
                    mma_f16(acc[mi][ni][0], acc[mi][ni][1],
                            acc[mi][ni][2], acc[mi][ni][3],
                            a[mi][0], a[mi][1], a[mi][2], a[mi][3],
                            b[ni][0], b[ni][1]);
        }
        __syncthreads();
    }

#pragma unroll
    for (int mi = 0; mi < 2; mi++) {
        int r0 = rowBase + warpRow + mi * 16 + gp;
        int r1 = r0 + 8;
        float d0 = (r0 < NN) ? g_dinv[r0] : 0.f;
        float d1 = (r1 < NN) ? g_dinv[r1] : 0.f;
#pragma unroll
        for (int ni = 0; ni < 4; ni++) {
            int c = warpCol + ni * 8 + tq * 2;
            if (r0 < NN) {
                if (c < NC)     g_h2[(size_t)r0 * NC + c]     = d0 * acc[mi][ni][0];
                if (c + 1 < NC) g_h2[(size_t)r0 * NC + c + 1] = d0 * acc[mi][ni][1];
            }
            if (r1 < NN) {
                if (c < NC)     g_h2[(size_t)r1 * NC + c]     = d1 * acc[mi][ni][2];
                if (c + 1 < NC) g_h2[(size_t)r1 * NC + c + 1] = d1 * acc[mi][ni][3];
            }
        }
    }
}

// ---------------- agg2: out[i,c] = dinv[i]*sum_{adj} h2[row,c] + b2[c] ----------------
__global__ __launch_bounds__(256) void k_agg2(const float* __restrict__ b2,
                                              float* __restrict__ out) {
    int node = blockIdx.x * 8 + (threadIdx.x >> 5);
    if (node >= NN) return;
    int lane = threadIdx.x & 31;
    int s = g_offs[node], e = g_offs[node + 1];
    float a0 = 0.f, a1 = 0.f;
    for (int p = s; p < e; p++) {
        int r = g_adj[p];
        const float* gp = g_h2 + (size_t)r * NC;
        a0 += gp[lane];
        if (lane + 32 < NC) a1 += gp[lane + 32];
    }
    float d = g_dinv[node];
    out[(size_t)node * NC + lane] = d * a0 + b2[lane];
    if (lane + 32 < NC)
        out[(size_t)node * NC + lane + 32] = d * a1 + b2[lane + 32];
}

// ---------------- launch ----------------
extern "C" void kernel_launch(void* const* d_in, const int* in_sizes, int n_in,
                              void* d_out, int out_size) {
    const float* x  = (const float*)d_in[0];
    const int*   ei = (const int*)d_in[1];   // [2, NE] int32
    const float* W1 = (const float*)d_in[2];
    const float* b1 = (const float*)d_in[3];
    const float* W2 = (const float*)d_in[4];
    const float* b2 = (const float*)d_in[5];
    float* out = (float*)d_out;

    const int* erow = ei;
    const int* ecol = ei + NE;

    // one-time host objects (created on the correctness call, before capture)
    static cudaStream_t s2 = nullptr;
    static cudaEvent_t evFork = nullptr, evJoin = nullptr;
    if (!s2) {
        cudaStreamCreateWithFlags(&s2, cudaStreamNonBlocking);
        cudaEventCreateWithFlags(&evFork, cudaEventDisableTiming);
        cudaEventCreateWithFlags(&evJoin, cudaEventDisableTiming);
        cudaFuncSetAttribute(k_gemm1_f16,
                             cudaFuncAttributeMaxDynamicSharedMemorySize, H1_SMEM_BYTES);
        cudaFuncSetAttribute(k_gemm2_f16,
                             cudaFuncAttributeMaxDynamicSharedMemorySize, H2_SMEM_BYTES);
    }

    // ---- fork: graph prep + W2 pack on side stream
    cudaEventRecord(evFork, 0);
    cudaStreamWaitEvent(s2, evFork, 0);
    k_w2p<<<((NH / 2) * 64 + 255) / 256, 256, 0, s2>>>(W2);
    k_init_deg<<<(NN + 255) / 256, 256, 0, s2>>>();
    k_count_deg<<<(NE + 255) / 256, 256, 0, s2>>>(ecol);
    k_scan_block<<<NSB, 512, 0, s2>>>();
    k_scan_finish2<<<(NN + 255) / 256, 256, 0, s2>>>();
    k_scatter<<<(NADJ + 255) / 256, 256, 0, s2>>>(erow, ecol);
    cudaEventRecord(evJoin, s2);

    // ---- main stream: W1 pack + layer 1 GEMM (fp32-x inline convert; overlaps prep)
    k_w1p<<<((DF / 2) * NH + 255) / 256, 256>>>(W1);
    dim3 g1(NH / 128, (NN + 127) / 128);
    k_gemm1_f16<<<g1, 128, H1_SMEM_BYTES>>>(x);

    // ---- join: everything below needs prep outputs
    cudaStreamWaitEvent(0, evJoin, 0);

    k_agg1<<<NN, 128>>>(b1);
    k_gemm2_f16<<<(NN + 127) / 128, 256, H2_SMEM_BYTES>>>();
    k_agg2<<<(NN + 7) / 8, 256>>>(b2, out);
}